// round 4
// baseline (speedup 1.0000x reference)
#include <cuda_runtime.h>

#define D_MODEL 1024
#define NHEAD   16
#define DK      64
#define BATCH   2
#define SEQ     2048
#define MTOT    (BATCH*SEQ)   // 4096

// ---------------- scratch (static device globals; no allocations) ----------
__device__ float g_Q[(size_t)BATCH*NHEAD*SEQ*DK];
__device__ float g_K[(size_t)BATCH*NHEAD*SEQ*DK];
__device__ float g_V[(size_t)BATCH*NHEAD*SEQ*DK];
__device__ float g_O[(size_t)MTOT*D_MODEL];

struct QKVArgs {
    const float* X[3];
    const float* W[3];
    const float* Bv[3];
};

// ---------------- shared GEMM mainloop: out[m,n] = sum_k X[m,k]*W[n,k] -----
// 128x128 block tile, BK=16, 256 threads, 8x8 micro-tile per thread.
__device__ __forceinline__ void gemm_mainloop(
    const float* __restrict__ X, const float* __restrict__ W,
    int m0, int n0, int tid, float acc[8][8],
    float (*As)[132], float (*Bs)[132])
{
    const int lrow = tid >> 2;            // 0..63
    const int lcol = (tid & 3) << 2;      // 0,4,8,12
    const int tx = tid & 15, ty = tid >> 4;

    for (int k0 = 0; k0 < D_MODEL; k0 += 16) {
        float4 a0 = *(const float4*)(X + (size_t)(m0 + lrow     ) * D_MODEL + k0 + lcol);
        float4 a1 = *(const float4*)(X + (size_t)(m0 + lrow + 64) * D_MODEL + k0 + lcol);
        float4 b0 = *(const float4*)(W + (size_t)(n0 + lrow     ) * D_MODEL + k0 + lcol);
        float4 b1 = *(const float4*)(W + (size_t)(n0 + lrow + 64) * D_MODEL + k0 + lcol);
        __syncthreads();
        As[lcol+0][lrow] = a0.x; As[lcol+1][lrow] = a0.y;
        As[lcol+2][lrow] = a0.z; As[lcol+3][lrow] = a0.w;
        As[lcol+0][lrow+64] = a1.x; As[lcol+1][lrow+64] = a1.y;
        As[lcol+2][lrow+64] = a1.z; As[lcol+3][lrow+64] = a1.w;
        Bs[lcol+0][lrow] = b0.x; Bs[lcol+1][lrow] = b0.y;
        Bs[lcol+2][lrow] = b0.z; Bs[lcol+3][lrow] = b0.w;
        Bs[lcol+0][lrow+64] = b1.x; Bs[lcol+1][lrow+64] = b1.y;
        Bs[lcol+2][lrow+64] = b1.z; Bs[lcol+3][lrow+64] = b1.w;
        __syncthreads();
        #pragma unroll
        for (int kk = 0; kk < 16; ++kk) {
            float am[8], bn[8];
            *(float4*)&am[0] = *(const float4*)&As[kk][ty*4];
            *(float4*)&am[4] = *(const float4*)&As[kk][64 + ty*4];
            *(float4*)&bn[0] = *(const float4*)&Bs[kk][tx*4];
            *(float4*)&bn[4] = *(const float4*)&Bs[kk][64 + tx*4];
            #pragma unroll
            for (int i = 0; i < 8; ++i)
                #pragma unroll
                for (int j = 0; j < 8; ++j)
                    acc[i][j] = fmaf(am[i], bn[j], acc[i][j]);
        }
    }
}

// ---------------- fused QKV projection: grid (8, 32, 3) --------------------
__global__ __launch_bounds__(256) void gemm_qkv_kernel(QKVArgs args) {
    __shared__ float As[16][132];
    __shared__ float Bs[16][132];
    const int z = blockIdx.z;
    const float* X    = args.X[z];
    const float* W    = args.W[z];
    const float* bias = args.Bv[z];
    float* outp = (z == 0) ? g_Q : (z == 1) ? g_K : g_V;

    const int m0 = blockIdx.y * 128;
    const int n0 = blockIdx.x * 128;
    const int tid = threadIdx.x;
    const int tx = tid & 15, ty = tid >> 4;

    float acc[8][8] = {};
    gemm_mainloop(X, W, m0, n0, tid, acc, As, Bs);

    float bv[8];
    #pragma unroll
    for (int j = 0; j < 4; ++j) {
        bv[j]     = bias[n0 +      tx*4 + j];
        bv[4 + j] = bias[n0 + 64 + tx*4 + j];
    }
    #pragma unroll
    for (int i = 0; i < 8; ++i) {
        int m = m0 + ty*4 + (i & 3) + ((i >= 4) ? 64 : 0);
        int bb = m >> 11;            // /SEQ
        int s  = m & (SEQ - 1);
        #pragma unroll
        for (int half = 0; half < 2; ++half) {
            int n = n0 + half*64 + tx*4;
            int h = n >> 6;
            int d = n & 63;
            float4 v;
            v.x = acc[i][half*4+0] + bv[half*4+0];
            v.y = acc[i][half*4+1] + bv[half*4+1];
            v.z = acc[i][half*4+2] + bv[half*4+2];
            v.w = acc[i][half*4+3] + bv[half*4+3];
            *(float4*)(outp + ((size_t)((bb*NHEAD + h)*SEQ + s)) * DK + d) = v;
        }
    }
}

// ---------------- output projection: grid (8, 32) --------------------------
__global__ __launch_bounds__(256) void gemm_out_kernel(
    const float* __restrict__ W, const float* __restrict__ bias,
    float* __restrict__ out)
{
    __shared__ float As[16][132];
    __shared__ float Bs[16][132];
    const int m0 = blockIdx.y * 128;
    const int n0 = blockIdx.x * 128;
    const int tid = threadIdx.x;
    const int tx = tid & 15, ty = tid >> 4;

    float acc[8][8] = {};
    gemm_mainloop(g_O, W, m0, n0, tid, acc, As, Bs);

    float bv[8];
    #pragma unroll
    for (int j = 0; j < 4; ++j) {
        bv[j]     = bias[n0 +      tx*4 + j];
        bv[4 + j] = bias[n0 + 64 + tx*4 + j];
    }
    #pragma unroll
    for (int i = 0; i < 8; ++i) {
        int m = m0 + ty*4 + (i & 3) + ((i >= 4) ? 64 : 0);
        #pragma unroll
        for (int half = 0; half < 2; ++half) {
            int n = n0 + half*64 + tx*4;
            float4 v;
            v.x = acc[i][half*4+0] + bv[half*4+0];
            v.y = acc[i][half*4+1] + bv[half*4+1];
            v.z = acc[i][half*4+2] + bv[half*4+2];
            v.w = acc[i][half*4+3] + bv[half*4+3];
            *(float4*)(out + (size_t)m * D_MODEL + n) = v;
        }
    }
}

// ---------------- flash attention: grid (32, 16, 2), 256 threads -----------
// Tiles: Br=64 queries x Bc=64 keys, d=64. Smem (exactly 48KB static):
//   Qt[d][r]  transposed+swizzled, pre-scaled by 1/sqrt(dk)
//   KPt       K transposed+swizzled, then reused for P transposed (Pt[j][r])
//   Vs[j][d]  natural
// Swizzle for transposed tiles: word = d*64 + 4*((r>>2) ^ (d>>2)) + (r&3).
__global__ __launch_bounds__(256) void attn_kernel() {
    __shared__ float Qt [64*64];
    __shared__ float KPt[64*64];
    __shared__ float Vs [64*64];

    const int qt = blockIdx.x;          // query tile
    const int h  = blockIdx.y;
    const int b  = blockIdx.z;
    const int tid = threadIdx.x;
    const int tx = tid & 15, ty = tid >> 4;

    const float* Qg = g_Q + ((size_t)(b*NHEAD + h)*SEQ + qt*64) * DK;
    const float* Kg = g_K + ((size_t)(b*NHEAD + h)*SEQ) * DK;
    const float* Vg = g_V + ((size_t)(b*NHEAD + h)*SEQ) * DK;

    const float SCALE = 0.125f;  // 1/sqrt(64)

    // load Q tile, transposed + scaled
    #pragma unroll
    for (int it = 0; it < 4; ++it) {
        int idx = tid + it*256;
        int r  = idx >> 4;
        int cc = idx & 15;
        float4 v = *(const float4*)(Qg + (size_t)r*DK + cc*4);
        int base = 4*((r >> 2) ^ cc) + (r & 3);
        int d0 = cc*4;
        Qt[(d0+0)*64 + base] = v.x * SCALE;
        Qt[(d0+1)*64 + base] = v.y * SCALE;
        Qt[(d0+2)*64 + base] = v.z * SCALE;
        Qt[(d0+3)*64 + base] = v.w * SCALE;
    }

    float m_i[4], l_i[4], o[4][4];
    #pragma unroll
    for (int i = 0; i < 4; ++i) {
        m_i[i] = -1e30f; l_i[i] = 0.f;
        #pragma unroll
        for (int u = 0; u < 4; ++u) o[i][u] = 0.f;
    }

    for (int t = 0; t < SEQ/64; ++t) {
        // load K (transposed+swizzled) and V (natural)
        #pragma unroll
        for (int it = 0; it < 4; ++it) {
            int idx = tid + it*256;
            int r  = idx >> 4;
            int cc = idx & 15;
            const float* kp = Kg + (size_t)(t*64 + r)*DK + cc*4;
            const float* vp = Vg + (size_t)(t*64 + r)*DK + cc*4;
            float4 kv = *(const float4*)kp;
            float4 vv = *(const float4*)vp;
            int base = 4*((r >> 2) ^ cc) + (r & 3);
            int d0 = cc*4;
            KPt[(d0+0)*64 + base] = kv.x;
            KPt[(d0+1)*64 + base] = kv.y;
            KPt[(d0+2)*64 + base] = kv.z;
            KPt[(d0+3)*64 + base] = kv.w;
            *(float4*)(Vs + r*64 + d0) = vv;
        }
        __syncthreads();

        // S = (Q*scale) K^T   [4x4 per thread]
        float s[4][4] = {};
        #pragma unroll 8
        for (int d = 0; d < 64; ++d) {
            float4 qa = *(const float4*)(Qt  + d*64 + 4*(ty ^ (d >> 2)));
            float4 kb = *(const float4*)(KPt + d*64 + 4*(tx ^ (d >> 2)));
            float qr[4] = {qa.x, qa.y, qa.z, qa.w};
            float kr[4] = {kb.x, kb.y, kb.z, kb.w};
            #pragma unroll
            for (int i = 0; i < 4; ++i)
                #pragma unroll
                for (int u = 0; u < 4; ++u)
                    s[i][u] = fmaf(qr[i], kr[u], s[i][u]);
        }

        // online softmax (row reductions across tx via shfl_xor, bits 0..3)
        #pragma unroll
        for (int i = 0; i < 4; ++i) {
            float mx = fmaxf(fmaxf(s[i][0], s[i][1]), fmaxf(s[i][2], s[i][3]));
            mx = fmaxf(mx, __shfl_xor_sync(0xffffffffu, mx, 1));
            mx = fmaxf(mx, __shfl_xor_sync(0xffffffffu, mx, 2));
            mx = fmaxf(mx, __shfl_xor_sync(0xffffffffu, mx, 4));
            mx = fmaxf(mx, __shfl_xor_sync(0xffffffffu, mx, 8));
            float mnew  = fmaxf(m_i[i], mx);
            float alpha = __expf(m_i[i] - mnew);
            float rs = 0.f;
            #pragma unroll
            for (int u = 0; u < 4; ++u) {
                float p = __expf(s[i][u] - mnew);
                s[i][u] = p;
                rs += p;
            }
            rs += __shfl_xor_sync(0xffffffffu, rs, 1);
            rs += __shfl_xor_sync(0xffffffffu, rs, 2);
            rs += __shfl_xor_sync(0xffffffffu, rs, 4);
            rs += __shfl_xor_sync(0xffffffffu, rs, 8);
            l_i[i] = l_i[i] * alpha + rs;
            m_i[i] = mnew;
            #pragma unroll
            for (int u = 0; u < 4; ++u) o[i][u] *= alpha;
        }
        __syncthreads();   // everyone done reading K before P overwrites it

        // write P transposed into KPt: Pt[j][r], j = 4*tx+u, r = 4*ty+i
        #pragma unroll
        for (int u = 0; u < 4; ++u) {
            int j = 4*tx + u;
            float4 pv = make_float4(s[0][u], s[1][u], s[2][u], s[3][u]);
            *(float4*)(KPt + j*64 + 4*(ty ^ tx)) = pv;
        }
        __syncthreads();

        // O += P @ V
        #pragma unroll 8
        for (int j = 0; j < 64; ++j) {
            float4 pa = *(const float4*)(KPt + j*64 + 4*(ty ^ (j >> 2)));
            float4 vb = *(const float4*)(Vs  + j*64 + 4*tx);
            float pr[4] = {pa.x, pa.y, pa.z, pa.w};
            float vr[4] = {vb.x, vb.y, vb.z, vb.w};
            #pragma unroll
            for (int i = 0; i < 4; ++i)
                #pragma unroll
                for (int u = 0; u < 4; ++u)
                    o[i][u] = fmaf(pr[i], vr[u], o[i][u]);
        }
        __syncthreads();   // before next tile overwrites KPt / Vs
    }

    // epilogue: O[b][s][h*64 + d] into [B, S, D_MODEL]
    float* Og = g_O + ((size_t)b*SEQ + qt*64) * D_MODEL + h*DK;
    #pragma unroll
    for (int i = 0; i < 4; ++i) {
        float inv = 1.0f / l_i[i];
        int r = 4*ty + i;
        float4 v = make_float4(o[i][0]*inv, o[i][1]*inv, o[i][2]*inv, o[i][3]*inv);
        *(float4*)(Og + (size_t)r*D_MODEL + 4*tx) = v;
    }
}

// ---------------- launcher --------------------------------------------------
extern "C" void kernel_launch(void* const* d_in, const int* in_sizes, int n_in,
                              void* d_out, int out_size) {
    const float* query = (const float*)d_in[0];
    const float* key   = (const float*)d_in[1];
    const float* value = (const float*)d_in[2];
    const float* Wq    = (const float*)d_in[3];
    const float* bq    = (const float*)d_in[4];
    const float* Wk    = (const float*)d_in[5];
    const float* bk    = (const float*)d_in[6];
    const float* Wv    = (const float*)d_in[7];
    const float* bv    = (const float*)d_in[8];
    const float* Wo    = (const float*)d_in[9];
    const float* bo    = (const float*)d_in[10];
    float* out = (float*)d_out;

    QKVArgs args;
    args.X[0] = query; args.X[1] = key; args.X[2] = value;
    args.W[0] = Wq;    args.W[1] = Wk;  args.W[2] = Wv;
    args.Bv[0] = bq;   args.Bv[1] = bk; args.Bv[2] = bv;

    dim3 gQKV(D_MODEL/128, MTOT/128, 3);   // (8, 32, 3)
    gemm_qkv_kernel<<<gQKV, 256>>>(args);

    dim3 gAtt(SEQ/64, NHEAD, BATCH);       // (32, 16, 2)
    attn_kernel<<<gAtt, 256>>>();

    dim3 gOut(D_MODEL/128, MTOT/128, 1);   // (8, 32)
    gemm_out_kernel<<<gOut, 256>>>(Wo, bo, out);
}

// round 6
// speedup vs baseline: 2.5735x; 2.5735x over previous
#include <cuda_runtime.h>
#include <cuda_bf16.h>
#include <stdint.h>

#define D_MODEL 1024
#define NHEAD   16
#define DK      64
#define BATCH   2
#define SEQ     2048
#define MTOT    (BATCH*SEQ)   // 4096

// ---------------- scratch (static device globals; no allocations) ----------
// bf16 hi/lo splits of raw inputs
__device__ __nv_bfloat16 g_qh[(size_t)MTOT*D_MODEL],    g_ql[(size_t)MTOT*D_MODEL];
__device__ __nv_bfloat16 g_kh[(size_t)MTOT*D_MODEL],    g_kl[(size_t)MTOT*D_MODEL];
__device__ __nv_bfloat16 g_vh[(size_t)MTOT*D_MODEL],    g_vl[(size_t)MTOT*D_MODEL];
__device__ __nv_bfloat16 g_wqh[(size_t)D_MODEL*D_MODEL], g_wql[(size_t)D_MODEL*D_MODEL];
__device__ __nv_bfloat16 g_wkh[(size_t)D_MODEL*D_MODEL], g_wkl[(size_t)D_MODEL*D_MODEL];
__device__ __nv_bfloat16 g_wvh[(size_t)D_MODEL*D_MODEL], g_wvl[(size_t)D_MODEL*D_MODEL];
__device__ __nv_bfloat16 g_woh[(size_t)D_MODEL*D_MODEL], g_wol[(size_t)D_MODEL*D_MODEL];
// projected Q/K/V splits, head-major [b][h][s][d]  (Q pre-scaled by 0.125*log2e)
__device__ __nv_bfloat16 g_pqh[(size_t)MTOT*D_MODEL],   g_pql[(size_t)MTOT*D_MODEL];
__device__ __nv_bfloat16 g_pkh[(size_t)MTOT*D_MODEL],   g_pkl[(size_t)MTOT*D_MODEL];
__device__ __nv_bfloat16 g_pvh[(size_t)MTOT*D_MODEL],   g_pvl[(size_t)MTOT*D_MODEL];
// attention output splits [b][s][h*64+d]
__device__ __nv_bfloat16 g_oh[(size_t)MTOT*D_MODEL],    g_ol[(size_t)MTOT*D_MODEL];

// ======================= low-level helpers (base ISA only) ================
__device__ __forceinline__ unsigned smem_u32(const void* p) {
    unsigned a;
    asm("{ .reg .u64 t; cvta.to.shared.u64 t, %1; cvt.u32.u64 %0, t; }" : "=r"(a) : "l"(p));
    return a;
}
__device__ __forceinline__ void cp16(unsigned dst, const void* src) {
    asm volatile("cp.async.cg.shared.global [%0], [%1], 16;" :: "r"(dst), "l"(src));
}
#define CP_COMMIT() asm volatile("cp.async.commit_group;" ::: "memory")
#define CP_WAIT1()  asm volatile("cp.async.wait_group 1;"  ::: "memory")

#define LDSM4(r, a) \
    asm volatile("ldmatrix.sync.aligned.m8n8.x4.shared.b16 {%0,%1,%2,%3}, [%4];" \
        : "=r"((r)[0]), "=r"((r)[1]), "=r"((r)[2]), "=r"((r)[3]) : "r"(a))
#define LDSM4T(r, a) \
    asm volatile("ldmatrix.sync.aligned.m8n8.x4.trans.shared.b16 {%0,%1,%2,%3}, [%4];" \
        : "=r"((r)[0]), "=r"((r)[1]), "=r"((r)[2]), "=r"((r)[3]) : "r"(a))

#define MMA4(d, a, b0, b1) \
    asm volatile("mma.sync.aligned.m16n8k16.row.col.f32.bf16.bf16.f32 " \
        "{%0,%1,%2,%3}, {%4,%5,%6,%7}, {%8,%9}, {%0,%1,%2,%3};" \
        : "+f"((d)[0]), "+f"((d)[1]), "+f"((d)[2]), "+f"((d)[3]) \
        : "r"((a)[0]), "r"((a)[1]), "r"((a)[2]), "r"((a)[3]), "r"(b0), "r"(b1))

__device__ __forceinline__ float fexp2(float x) {
    float y; asm("ex2.approx.f32 %0, %1;" : "=f"(y) : "f"(x)); return y;
}
// pack (x,y) -> bf16x2 hi-part and residual lo-part
__device__ __forceinline__ void split2(float x, float y, unsigned& hi, unsigned& lo) {
    __nv_bfloat162 h = __float22bfloat162_rn(make_float2(x, y));
    float2 hf = __bfloat1622float2(h);
    __nv_bfloat162 l = __float22bfloat162_rn(make_float2(x - hf.x, y - hf.y));
    hi = *(unsigned*)&h; lo = *(unsigned*)&l;
}

// ======================= split kernel: fp32 -> bf16 hi/lo ===================
__global__ __launch_bounds__(256) void split_all(
    const float* q, const float* k, const float* v,
    const float* wq, const float* wk, const float* wv, const float* wo)
{
    const int z = blockIdx.y;
    const float* src; __nv_bfloat16 *dh, *dl; int n4;
    const int NA = MTOT*D_MODEL/4, NW = D_MODEL*D_MODEL/4;
    switch (z) {
        case 0: src = q;  dh = g_qh;  dl = g_ql;  n4 = NA; break;
        case 1: src = k;  dh = g_kh;  dl = g_kl;  n4 = NA; break;
        case 2: src = v;  dh = g_vh;  dl = g_vl;  n4 = NA; break;
        case 3: src = wq; dh = g_wqh; dl = g_wql; n4 = NW; break;
        case 4: src = wk; dh = g_wkh; dl = g_wkl; n4 = NW; break;
        case 5: src = wv; dh = g_wvh; dl = g_wvl; n4 = NW; break;
        default:src = wo; dh = g_woh; dl = g_wol; n4 = NW; break;
    }
    for (int i = blockIdx.x * blockDim.x + threadIdx.x; i < n4; i += gridDim.x * blockDim.x) {
        float4 vv = ((const float4*)src)[i];
        unsigned h0, l0, h1, l1;
        split2(vv.x, vv.y, h0, l0);
        split2(vv.z, vv.w, h1, l1);
        ((unsigned*)dh)[2*i] = h0; ((unsigned*)dh)[2*i+1] = h1;
        ((unsigned*)dl)[2*i] = l0; ((unsigned*)dl)[2*i+1] = l1;
    }
}

// ======================= HMMA GEMM core =====================================
// C[m,n] = sum_k A[m,k]*B[n,k]; bf16 4-term split, fp32 accum.
// BM=BN=128, BK=32, 256 thr (8 warps = 4x2), warp tile 32x64.
// Stage (32KB): Ah(8K) Al(8K) Bh(8K) Bl(8K); tile = 128 rows x 32 bf16,
// 16B-chunk swizzle: physchunk = kc ^ ((row>>1)&3). 3 stages = 96KB.
#define G_STAGE 32768
#define G_SMEM  (3*G_STAGE)

__device__ __forceinline__ void gemm_load_stage(
    unsigned st, const __nv_bfloat16* Ah, const __nv_bfloat16* Al,
    const __nv_bfloat16* Bh, const __nv_bfloat16* Bl,
    int m0, int n0, int k0, int tid)
{
    const __nv_bfloat16* srcs[4] = {Ah, Al, Bh, Bl};
    #pragma unroll
    for (int tt = 0; tt < 4; ++tt) {
        const int r0 = (tt < 2) ? m0 : n0;
        const __nv_bfloat16* s = srcs[tt];
        #pragma unroll
        for (int i = 0; i < 2; ++i) {
            int idx = tid + i * 256;         // 0..511 chunks
            int row = idx >> 2, kc = idx & 3;
            unsigned d = st + tt * 8192 + row * 64 + (((kc ^ ((row >> 1) & 3))) << 4);
            cp16(d, s + (size_t)(r0 + row) * D_MODEL + k0 + kc * 8);
        }
    }
}

__device__ __forceinline__ void gemm_compute(
    const __nv_bfloat16* Ah, const __nv_bfloat16* Al,
    const __nv_bfloat16* Bh, const __nv_bfloat16* Bl,
    int m0, int n0, unsigned sb, int tid, float acc[2][8][4])
{
    const int lane = tid & 31, wid = tid >> 5;
    const int wm = wid & 3, wn = wid >> 2;

    gemm_load_stage(sb,            Ah, Al, Bh, Bl, m0, n0, 0,  tid); CP_COMMIT();
    gemm_load_stage(sb + G_STAGE,  Ah, Al, Bh, Bl, m0, n0, 32, tid); CP_COMMIT();

    for (int it = 0; it < 32; ++it) {
        CP_WAIT1();
        __syncthreads();
        if (it + 2 < 32)
            gemm_load_stage(sb + ((it + 2) % 3) * G_STAGE, Ah, Al, Bh, Bl,
                            m0, n0, (it + 2) * 32, tid);
        CP_COMMIT();
        const unsigned st = sb + (it % 3) * G_STAGE;
        #pragma unroll
        for (int ks = 0; ks < 2; ++ks) {
            unsigned aH[2][4], aL[2][4];
            #pragma unroll
            for (int mt = 0; mt < 2; ++mt) {
                int row = wm * 32 + mt * 16 + (lane & 15);
                int kc  = 2 * ks + (lane >> 4);
                unsigned off = row * 64 + (((kc ^ ((row >> 1) & 3))) << 4);
                LDSM4(aH[mt], st + off);
                LDSM4(aL[mt], st + 8192 + off);
            }
            #pragma unroll
            for (int q = 0; q < 4; ++q) {
                unsigned bH[4], bL[4];
                int row = wn * 64 + q * 16 + (lane & 7) + 8 * ((lane >> 4) & 1);
                int kc  = 2 * ks + ((lane >> 3) & 1);
                unsigned off = row * 64 + (((kc ^ ((row >> 1) & 3))) << 4);
                LDSM4(bH, st + 16384 + off);
                LDSM4(bL, st + 24576 + off);
                #pragma unroll
                for (int mt = 0; mt < 2; ++mt) {
                    MMA4(acc[mt][2*q],   aH[mt], bH[0], bH[1]);
                    MMA4(acc[mt][2*q],   aH[mt], bL[0], bL[1]);
                    MMA4(acc[mt][2*q],   aL[mt], bH[0], bH[1]);
                    MMA4(acc[mt][2*q],   aL[mt], bL[0], bL[1]);
                    MMA4(acc[mt][2*q+1], aH[mt], bH[2], bH[3]);
                    MMA4(acc[mt][2*q+1], aH[mt], bL[2], bL[3]);
                    MMA4(acc[mt][2*q+1], aL[mt], bH[2], bH[3]);
                    MMA4(acc[mt][2*q+1], aL[mt], bL[2], bL[3]);
                }
            }
        }
    }
}

// ---------------- QKV projection: grid (8, 32, 3) --------------------------
__global__ __launch_bounds__(256) void tc_qkv(
    const float* __restrict__ bq, const float* __restrict__ bk,
    const float* __restrict__ bv)
{
    extern __shared__ char smem[];
    const unsigned sb = smem_u32(smem);
    const int z = blockIdx.z;
    const __nv_bfloat16 *Ah, *Al, *Bh, *Bl;
    __nv_bfloat16 *dh, *dl;
    const float* bias;
    float scale;
    if (z == 0)      { Ah=g_qh; Al=g_ql; Bh=g_wqh; Bl=g_wql; dh=g_pqh; dl=g_pql; bias=bq; scale=0.18033688f; }
    else if (z == 1) { Ah=g_kh; Al=g_kl; Bh=g_wkh; Bl=g_wkl; dh=g_pkh; dl=g_pkl; bias=bk; scale=1.0f; }
    else             { Ah=g_vh; Al=g_vl; Bh=g_wvh; Bl=g_wvl; dh=g_pvh; dl=g_pvl; bias=bv; scale=1.0f; }

    const int n0 = blockIdx.x * 128, m0 = blockIdx.y * 128;
    const int tid = threadIdx.x, lane = tid & 31, wid = tid >> 5;
    const int wm = wid & 3, wn = wid >> 2;

    float acc[2][8][4] = {};
    gemm_compute(Ah, Al, Bh, Bl, m0, n0, sb, tid, acc);

    #pragma unroll
    for (int nt = 0; nt < 8; ++nt) {
        int n = n0 + wn * 64 + nt * 8 + (lane & 3) * 2;
        float b0v = bias[n], b1v = bias[n + 1];
        int hd = n >> 6, d = n & 63;
        #pragma unroll
        for (int mt = 0; mt < 2; ++mt) {
            #pragma unroll
            for (int half = 0; half < 2; ++half) {
                int m = m0 + wm * 32 + mt * 16 + (lane >> 2) + 8 * half;
                float x = (acc[mt][nt][2*half+0] + b0v) * scale;
                float y = (acc[mt][nt][2*half+1] + b1v) * scale;
                unsigned hi, lo; split2(x, y, hi, lo);
                size_t dst = ((size_t)((m >> 11) * NHEAD + hd) * SEQ + (m & (SEQ-1))) * DK + d;
                *(unsigned*)(dh + dst) = hi;
                *(unsigned*)(dl + dst) = lo;
            }
        }
    }
}

// ---------------- output projection: grid (8, 32) --------------------------
__global__ __launch_bounds__(256) void tc_out(
    const float* __restrict__ bias, float* __restrict__ out)
{
    extern __shared__ char smem[];
    const unsigned sb = smem_u32(smem);
    const int n0 = blockIdx.x * 128, m0 = blockIdx.y * 128;
    const int tid = threadIdx.x, lane = tid & 31, wid = tid >> 5;
    const int wm = wid & 3, wn = wid >> 2;

    float acc[2][8][4] = {};
    gemm_compute(g_oh, g_ol, g_woh, g_wol, m0, n0, sb, tid, acc);

    #pragma unroll
    for (int nt = 0; nt < 8; ++nt) {
        int n = n0 + wn * 64 + nt * 8 + (lane & 3) * 2;
        float b0v = bias[n], b1v = bias[n + 1];
        #pragma unroll
        for (int mt = 0; mt < 2; ++mt) {
            #pragma unroll
            for (int half = 0; half < 2; ++half) {
                int m = m0 + wm * 32 + mt * 16 + (lane >> 2) + 8 * half;
                float2 vv = make_float2(acc[mt][nt][2*half+0] + b0v,
                                        acc[mt][nt][2*half+1] + b1v);
                *(float2*)(out + (size_t)m * D_MODEL + n) = vv;
            }
        }
    }
}

// ---------------- flash attention on HMMA: grid (16, 16, 2), 256 thr -------
// Br=128 q-rows/CTA (warp w owns rows 16w..16w+15), Bc=64 kv-rows/tile.
// SMEM: Qh 16K @0, Ql 16K @16K, 3 KV stages (32KB each: kh,kl,vh,vl 8K) @32K.
// Row layout 64 bf16 = 128B; chunk swizzle: physchunk = dc ^ (row&7).
#define A_STAGE 32768
#define A_SMEM  (32768 + 3*A_STAGE)

__device__ __forceinline__ void attn_load_stage(
    unsigned st, const __nv_bfloat16* kh, const __nv_bfloat16* kl,
    const __nv_bfloat16* vh, const __nv_bfloat16* vl, size_t base, int tid)
{
    const __nv_bfloat16* srcs[4] = {kh, kl, vh, vl};
    #pragma unroll
    for (int tt = 0; tt < 4; ++tt) {
        const __nv_bfloat16* s = srcs[tt];
        #pragma unroll
        for (int i = 0; i < 2; ++i) {
            int idx = tid + i * 256;         // 0..511 chunks (64 rows x 8)
            int row = idx >> 3, dc = idx & 7;
            unsigned d = st + tt * 8192 + row * 128 + (((dc ^ (row & 7))) << 4);
            cp16(d, s + base + (size_t)row * DK + dc * 8);
        }
    }
}

__global__ __launch_bounds__(256) void attn_mma() {
    extern __shared__ char smem[];
    const unsigned sb = smem_u32(smem);
    const int tid = threadIdx.x, lane = tid & 31, w = tid >> 5;
    const int qt = blockIdx.x, h = blockIdx.y, b = blockIdx.z;

    const size_t headoff = ((size_t)(b * NHEAD + h)) * SEQ * DK;
    const __nv_bfloat16* Qh = g_pqh + headoff + (size_t)qt * 128 * DK;
    const __nv_bfloat16* Ql = g_pql + headoff + (size_t)qt * 128 * DK;
    const __nv_bfloat16* Kh = g_pkh + headoff;
    const __nv_bfloat16* Kl = g_pkl + headoff;
    const __nv_bfloat16* Vh = g_pvh + headoff;
    const __nv_bfloat16* Vl = g_pvl + headoff;

    const unsigned SQH = sb, SQL = sb + 16384, ST0 = sb + 32768;

    attn_load_stage(ST0,           Kh, Kl, Vh, Vl, 0,        tid); CP_COMMIT();
    attn_load_stage(ST0 + A_STAGE, Kh, Kl, Vh, Vl, 64 * DK,  tid); CP_COMMIT();

    // load Q tiles (plain LDG/STS, swizzled)
    #pragma unroll
    for (int tile = 0; tile < 2; ++tile) {
        const __nv_bfloat16* src = tile ? Ql : Qh;
        char* dst = smem + tile * 16384;
        #pragma unroll
        for (int i = 0; i < 4; ++i) {
            int idx = tid + i * 256;         // 0..1023 (128 rows x 8)
            int row = idx >> 3, dc = idx & 7;
            uint4 v = *(const uint4*)(src + (size_t)row * DK + dc * 8);
            *(uint4*)(dst + row * 128 + (((dc ^ (row & 7))) << 4)) = v;
        }
    }

    float s_m[2] = {-1e30f, -1e30f}, s_l[2] = {0.f, 0.f};
    float o[8][4] = {};

    for (int t = 0; t < 32; ++t) {
        CP_WAIT1();
        __syncthreads();
        if (t + 2 < 32)
            attn_load_stage(ST0 + ((t + 2) % 3) * A_STAGE, Kh, Kl, Vh, Vl,
                            (size_t)(t + 2) * 64 * DK, tid);
        CP_COMMIT();
        const unsigned st = ST0 + (t % 3) * A_STAGE;

        // ---- S = Q K^T (3-term bf16 split; Q pre-scaled) ----
        float s[8][4] = {};
        #pragma unroll
        for (int ks = 0; ks < 4; ++ks) {
            unsigned qa_h[4], qa_l[4];
            {
                int row = 16 * w + (lane & 15);
                int dc  = 2 * ks + (lane >> 4);
                unsigned off = row * 128 + (((dc ^ (row & 7))) << 4);
                LDSM4(qa_h, SQH + off);
                LDSM4(qa_l, SQL + off);
            }
            #pragma unroll
            for (int q4 = 0; q4 < 4; ++q4) {
                unsigned bh[4], bl[4];
                int krow = q4 * 16 + (lane & 7) + 8 * ((lane >> 4) & 1);
                int kdc  = 2 * ks + ((lane >> 3) & 1);
                unsigned off = krow * 128 + (((kdc ^ (krow & 7))) << 4);
                LDSM4(bh, st + off);
                LDSM4(bl, st + 8192 + off);
                MMA4(s[2*q4],   qa_h, bh[0], bh[1]);
                MMA4(s[2*q4],   qa_h, bl[0], bl[1]);
                MMA4(s[2*q4],   qa_l, bh[0], bh[1]);
                MMA4(s[2*q4+1], qa_h, bh[2], bh[3]);
                MMA4(s[2*q4+1], qa_h, bl[2], bl[3]);
                MMA4(s[2*q4+1], qa_l, bh[2], bh[3]);
            }
        }

        // ---- online softmax (base-2 domain; rows r0=lane>>2+16w, r1=+8) ----
        #pragma unroll
        for (int r = 0; r < 2; ++r) {
            float mx = -1e30f;
            #pragma unroll
            for (int nt = 0; nt < 8; ++nt)
                mx = fmaxf(mx, fmaxf(s[nt][2*r], s[nt][2*r+1]));
            mx = fmaxf(mx, __shfl_xor_sync(0xffffffffu, mx, 1));
            mx = fmaxf(mx, __shfl_xor_sync(0xffffffffu, mx, 2));
            float mnew  = fmaxf(s_m[r], mx);
            float alpha = fexp2(s_m[r] - mnew);
            float rs = 0.f;
            #pragma unroll
            for (int nt = 0; nt < 8; ++nt) {
                float p0 = fexp2(s[nt][2*r]   - mnew);
                float p1 = fexp2(s[nt][2*r+1] - mnew);
                s[nt][2*r] = p0; s[nt][2*r+1] = p1;
                rs += p0 + p1;
            }
            rs += __shfl_xor_sync(0xffffffffu, rs, 1);
            rs += __shfl_xor_sync(0xffffffffu, rs, 2);
            s_l[r] = s_l[r] * alpha + rs;
            s_m[r] = mnew;
            #pragma unroll
            for (int nt = 0; nt < 8; ++nt) { o[nt][2*r] *= alpha; o[nt][2*r+1] *= alpha; }
        }

        // ---- O += P V (P repacked as A-frags; V via ldmatrix.trans) ----
        #pragma unroll
        for (int ks = 0; ks < 4; ++ks) {
            unsigned pa_h[4], pa_l[4];
            #pragma unroll
            for (int e = 0; e < 4; ++e) {
                int nt = 2 * ks + (e >> 1);
                float x = s[nt][(e & 1) * 2], y = s[nt][(e & 1) * 2 + 1];
                split2(x, y, pa_h[e], pa_l[e]);
            }
            #pragma unroll
            for (int d4 = 0; d4 < 4; ++d4) {
                unsigned vhf[4], vlf[4];
                int vrow = 16 * ks + (lane & 15);
                int vdc  = 2 * d4 + (lane >> 4);
                unsigned off = vrow * 128 + (((vdc ^ (vrow & 7))) << 4);
                LDSM4T(vhf, st + 16384 + off);
                LDSM4T(vlf, st + 24576 + off);
                MMA4(o[2*d4],   pa_h, vhf[0], vhf[1]);
                MMA4(o[2*d4],   pa_h, vlf[0], vlf[1]);
                MMA4(o[2*d4],   pa_l, vhf[0], vhf[1]);
                MMA4(o[2*d4+1], pa_h, vhf[2], vhf[3]);
                MMA4(o[2*d4+1], pa_h, vlf[2], vlf[3]);
                MMA4(o[2*d4+1], pa_l, vhf[2], vhf[3]);
            }
        }
    }

    // ---- epilogue: O/l, split to bf16 h/l at [b][s][h*64+d] ----
    float inv[2] = {1.f / s_l[0], 1.f / s_l[1]};
    #pragma unroll
    for (int nt = 0; nt < 8; ++nt) {
        int d = h * DK + nt * 8 + (lane & 3) * 2;
        #pragma unroll
        for (int r = 0; r < 2; ++r) {
            int srow = qt * 128 + 16 * w + (lane >> 2) + 8 * r;
            float x = o[nt][2*r] * inv[r], y = o[nt][2*r+1] * inv[r];
            unsigned hi, lo; split2(x, y, hi, lo);
            size_t dst = (size_t)(b * SEQ + srow) * D_MODEL + d;
            *(unsigned*)(g_oh + dst) = hi;
            *(unsigned*)(g_ol + dst) = lo;
        }
    }
}

// ---------------- launcher --------------------------------------------------
extern "C" void kernel_launch(void* const* d_in, const int* in_sizes, int n_in,
                              void* d_out, int out_size) {
    const float* query = (const float*)d_in[0];
    const float* key   = (const float*)d_in[1];
    const float* value = (const float*)d_in[2];
    const float* Wq    = (const float*)d_in[3];
    const float* bq    = (const float*)d_in[4];
    const float* Wk    = (const float*)d_in[5];
    const float* bk    = (const float*)d_in[6];
    const float* Wv    = (const float*)d_in[7];
    const float* bv    = (const float*)d_in[8];
    const float* Wo    = (const float*)d_in[9];
    const float* bo    = (const float*)d_in[10];
    float* out = (float*)d_out;

    static int configured = 0;
    cudaFuncSetAttribute(tc_qkv,   cudaFuncAttributeMaxDynamicSharedMemorySize, G_SMEM);
    cudaFuncSetAttribute(tc_out,   cudaFuncAttributeMaxDynamicSharedMemorySize, G_SMEM);
    cudaFuncSetAttribute(attn_mma, cudaFuncAttributeMaxDynamicSharedMemorySize, A_SMEM);
    (void)configured;

    dim3 gS(592, 7);
    split_all<<<gS, 256>>>(query, key, value, Wq, Wk, Wv, Wo);

    dim3 gQKV(D_MODEL / 128, MTOT / 128, 3);   // (8, 32, 3)
    tc_qkv<<<gQKV, 256, G_SMEM>>>(bq, bk, bv);

    dim3 gAtt(SEQ / 128, NHEAD, BATCH);        // (16, 16, 2)
    attn_mma<<<gAtt, 256, A_SMEM>>>();

    dim3 gOut(D_MODEL / 128, MTOT / 128, 1);   // (8, 32)
    tc_out<<<gOut, 256, G_SMEM>>>(bo, out);
}

// round 7
// speedup vs baseline: 3.1216x; 1.2130x over previous
#include <cuda_runtime.h>
#include <cuda_bf16.h>
#include <stdint.h>

#define D_MODEL 1024
#define NHEAD   16
#define DK      64
#define BATCH   2
#define SEQ     2048
#define MTOT    (BATCH*SEQ)   // 4096

// ---------------- scratch (static device globals; no allocations) ----------
__device__ __nv_bfloat16 g_qh[(size_t)MTOT*D_MODEL],    g_ql[(size_t)MTOT*D_MODEL];
__device__ __nv_bfloat16 g_kh[(size_t)MTOT*D_MODEL],    g_kl[(size_t)MTOT*D_MODEL];
__device__ __nv_bfloat16 g_vh[(size_t)MTOT*D_MODEL],    g_vl[(size_t)MTOT*D_MODEL];
__device__ __nv_bfloat16 g_wqh[(size_t)D_MODEL*D_MODEL], g_wql[(size_t)D_MODEL*D_MODEL];
__device__ __nv_bfloat16 g_wkh[(size_t)D_MODEL*D_MODEL], g_wkl[(size_t)D_MODEL*D_MODEL];
__device__ __nv_bfloat16 g_wvh[(size_t)D_MODEL*D_MODEL], g_wvl[(size_t)D_MODEL*D_MODEL];
__device__ __nv_bfloat16 g_woh[(size_t)D_MODEL*D_MODEL], g_wol[(size_t)D_MODEL*D_MODEL];
// projected Q/K/V splits, head-major [b][h][s][d]  (Q pre-scaled by 0.125*log2e)
__device__ __nv_bfloat16 g_pqh[(size_t)MTOT*D_MODEL],   g_pql[(size_t)MTOT*D_MODEL];
__device__ __nv_bfloat16 g_pkh[(size_t)MTOT*D_MODEL],   g_pkl[(size_t)MTOT*D_MODEL];
__device__ __nv_bfloat16 g_pvh[(size_t)MTOT*D_MODEL],   g_pvl[(size_t)MTOT*D_MODEL];
// attention output splits [b][s][h*64+d]
__device__ __nv_bfloat16 g_oh[(size_t)MTOT*D_MODEL],    g_ol[(size_t)MTOT*D_MODEL];

// ======================= low-level helpers (base ISA only) ================
__device__ __forceinline__ unsigned smem_u32(const void* p) {
    unsigned a;
    asm("{ .reg .u64 t; cvta.to.shared.u64 t, %1; cvt.u32.u64 %0, t; }" : "=r"(a) : "l"(p));
    return a;
}
__device__ __forceinline__ void cp16(unsigned dst, const void* src) {
    asm volatile("cp.async.cg.shared.global [%0], [%1], 16;" :: "r"(dst), "l"(src));
}
#define CP_COMMIT() asm volatile("cp.async.commit_group;" ::: "memory")
#define CP_WAIT1()  asm volatile("cp.async.wait_group 1;"  ::: "memory")

#define LDSM4(r, a) \
    asm volatile("ldmatrix.sync.aligned.m8n8.x4.shared.b16 {%0,%1,%2,%3}, [%4];" \
        : "=r"((r)[0]), "=r"((r)[1]), "=r"((r)[2]), "=r"((r)[3]) : "r"(a))
#define LDSM4T(r, a) \
    asm volatile("ldmatrix.sync.aligned.m8n8.x4.trans.shared.b16 {%0,%1,%2,%3}, [%4];" \
        : "=r"((r)[0]), "=r"((r)[1]), "=r"((r)[2]), "=r"((r)[3]) : "r"(a))

#define MMA4(d, a, b0, b1) \
    asm volatile("mma.sync.aligned.m16n8k16.row.col.f32.bf16.bf16.f32 " \
        "{%0,%1,%2,%3}, {%4,%5,%6,%7}, {%8,%9}, {%0,%1,%2,%3};" \
        : "+f"((d)[0]), "+f"((d)[1]), "+f"((d)[2]), "+f"((d)[3]) \
        : "r"((a)[0]), "r"((a)[1]), "r"((a)[2]), "r"((a)[3]), "r"(b0), "r"(b1))

__device__ __forceinline__ float fexp2(float x) {
    float y; asm("ex2.approx.f32 %0, %1;" : "=f"(y) : "f"(x)); return y;
}
__device__ __forceinline__ void split2(float x, float y, unsigned& hi, unsigned& lo) {
    __nv_bfloat162 h = __float22bfloat162_rn(make_float2(x, y));
    float2 hf = __bfloat1622float2(h);
    __nv_bfloat162 l = __float22bfloat162_rn(make_float2(x - hf.x, y - hf.y));
    hi = *(unsigned*)&h; lo = *(unsigned*)&l;
}

// ======================= split kernel: fp32 -> bf16 hi/lo ===================
__global__ __launch_bounds__(256) void split_all(
    const float* q, const float* k, const float* v,
    const float* wq, const float* wk, const float* wv, const float* wo)
{
    const int z = blockIdx.y;
    const float* src; __nv_bfloat16 *dh, *dl; int n4;
    const int NA = MTOT*D_MODEL/4, NW = D_MODEL*D_MODEL/4;
    switch (z) {
        case 0: src = q;  dh = g_qh;  dl = g_ql;  n4 = NA; break;
        case 1: src = k;  dh = g_kh;  dl = g_kl;  n4 = NA; break;
        case 2: src = v;  dh = g_vh;  dl = g_vl;  n4 = NA; break;
        case 3: src = wq; dh = g_wqh; dl = g_wql; n4 = NW; break;
        case 4: src = wk; dh = g_wkh; dl = g_wkl; n4 = NW; break;
        case 5: src = wv; dh = g_wvh; dl = g_wvl; n4 = NW; break;
        default:src = wo; dh = g_woh; dl = g_wol; n4 = NW; break;
    }
    for (int i = blockIdx.x * blockDim.x + threadIdx.x; i < n4; i += gridDim.x * blockDim.x) {
        float4 vv = ((const float4*)src)[i];
        unsigned h0, l0, h1, l1;
        split2(vv.x, vv.y, h0, l0);
        split2(vv.z, vv.w, h1, l1);
        ((unsigned*)dh)[2*i] = h0; ((unsigned*)dh)[2*i+1] = h1;
        ((unsigned*)dl)[2*i] = l0; ((unsigned*)dl)[2*i+1] = l1;
    }
}

// ======================= HMMA GEMM core (3-term bf16 split) ================
// BM=BN=128, BK=32, 256 thr (8 warps = 4x2), warp tile 32x64, 3 stages.
#define G_STAGE 32768
#define G_SMEM  (3*G_STAGE)

__device__ __forceinline__ void gemm_load_stage(
    unsigned st, const __nv_bfloat16* Ah, const __nv_bfloat16* Al,
    const __nv_bfloat16* Bh, const __nv_bfloat16* Bl,
    int m0, int n0, int k0, int tid)
{
    const __nv_bfloat16* srcs[4] = {Ah, Al, Bh, Bl};
    #pragma unroll
    for (int tt = 0; tt < 4; ++tt) {
        const int r0 = (tt < 2) ? m0 : n0;
        const __nv_bfloat16* s = srcs[tt];
        #pragma unroll
        for (int i = 0; i < 2; ++i) {
            int idx = tid + i * 256;
            int row = idx >> 2, kc = idx & 3;
            unsigned d = st + tt * 8192 + row * 64 + (((kc ^ ((row >> 1) & 3))) << 4);
            cp16(d, s + (size_t)(r0 + row) * D_MODEL + k0 + kc * 8);
        }
    }
}

__device__ __forceinline__ void gemm_compute(
    const __nv_bfloat16* Ah, const __nv_bfloat16* Al,
    const __nv_bfloat16* Bh, const __nv_bfloat16* Bl,
    int m0, int n0, unsigned sb, int tid, float acc[2][8][4])
{
    const int lane = tid & 31, wid = tid >> 5;
    const int wm = wid & 3, wn = wid >> 2;

    gemm_load_stage(sb,            Ah, Al, Bh, Bl, m0, n0, 0,  tid); CP_COMMIT();
    gemm_load_stage(sb + G_STAGE,  Ah, Al, Bh, Bl, m0, n0, 32, tid); CP_COMMIT();

    for (int it = 0; it < 32; ++it) {
        CP_WAIT1();
        __syncthreads();
        if (it + 2 < 32)
            gemm_load_stage(sb + ((it + 2) % 3) * G_STAGE, Ah, Al, Bh, Bl,
                            m0, n0, (it + 2) * 32, tid);
        CP_COMMIT();
        const unsigned st = sb + (it % 3) * G_STAGE;
        #pragma unroll
        for (int ks = 0; ks < 2; ++ks) {
            unsigned aH[2][4], aL[2][4];
            #pragma unroll
            for (int mt = 0; mt < 2; ++mt) {
                int row = wm * 32 + mt * 16 + (lane & 15);
                int kc  = 2 * ks + (lane >> 4);
                unsigned off = row * 64 + (((kc ^ ((row >> 1) & 3))) << 4);
                LDSM4(aH[mt], st + off);
                LDSM4(aL[mt], st + 8192 + off);
            }
            #pragma unroll
            for (int q = 0; q < 4; ++q) {
                unsigned bH[4], bL[4];
                int row = wn * 64 + q * 16 + (lane & 7) + 8 * ((lane >> 4) & 1);
                int kc  = 2 * ks + ((lane >> 3) & 1);
                unsigned off = row * 64 + (((kc ^ ((row >> 1) & 3))) << 4);
                LDSM4(bH, st + 16384 + off);
                LDSM4(bL, st + 24576 + off);
                #pragma unroll
                for (int mt = 0; mt < 2; ++mt) {
                    MMA4(acc[mt][2*q],   aH[mt], bH[0], bH[1]);
                    MMA4(acc[mt][2*q],   aH[mt], bL[0], bL[1]);
                    MMA4(acc[mt][2*q],   aL[mt], bH[0], bH[1]);
                    MMA4(acc[mt][2*q+1], aH[mt], bH[2], bH[3]);
                    MMA4(acc[mt][2*q+1], aH[mt], bL[2], bL[3]);
                    MMA4(acc[mt][2*q+1], aL[mt], bH[2], bH[3]);
                }
            }
        }
    }
}

// ---------------- QKV projection: grid (8, 32, 3) --------------------------
__global__ __launch_bounds__(256) void tc_qkv(
    const float* __restrict__ bq, const float* __restrict__ bk,
    const float* __restrict__ bv)
{
    extern __shared__ char smem[];
    const unsigned sb = smem_u32(smem);
    const int z = blockIdx.z;
    const __nv_bfloat16 *Ah, *Al, *Bh, *Bl;
    __nv_bfloat16 *dh, *dl;
    const float* bias;
    float scale;
    if (z == 0)      { Ah=g_qh; Al=g_ql; Bh=g_wqh; Bl=g_wql; dh=g_pqh; dl=g_pql; bias=bq; scale=0.18033688f; }
    else if (z == 1) { Ah=g_kh; Al=g_kl; Bh=g_wkh; Bl=g_wkl; dh=g_pkh; dl=g_pkl; bias=bk; scale=1.0f; }
    else             { Ah=g_vh; Al=g_vl; Bh=g_wvh; Bl=g_wvl; dh=g_pvh; dl=g_pvl; bias=bv; scale=1.0f; }

    const int n0 = blockIdx.x * 128, m0 = blockIdx.y * 128;
    const int tid = threadIdx.x, lane = tid & 31, wid = tid >> 5;
    const int wm = wid & 3, wn = wid >> 2;

    float acc[2][8][4] = {};
    gemm_compute(Ah, Al, Bh, Bl, m0, n0, sb, tid, acc);

    #pragma unroll
    for (int nt = 0; nt < 8; ++nt) {
        int n = n0 + wn * 64 + nt * 8 + (lane & 3) * 2;
        float b0v = bias[n], b1v = bias[n + 1];
        int hd = n >> 6, d = n & 63;
        #pragma unroll
        for (int mt = 0; mt < 2; ++mt) {
            #pragma unroll
            for (int half = 0; half < 2; ++half) {
                int m = m0 + wm * 32 + mt * 16 + (lane >> 2) + 8 * half;
                float x = (acc[mt][nt][2*half+0] + b0v) * scale;
                float y = (acc[mt][nt][2*half+1] + b1v) * scale;
                unsigned hi, lo; split2(x, y, hi, lo);
                size_t dst = ((size_t)((m >> 11) * NHEAD + hd) * SEQ + (m & (SEQ-1))) * DK + d;
                *(unsigned*)(dh + dst) = hi;
                *(unsigned*)(dl + dst) = lo;
            }
        }
    }
}

// ---------------- output projection: grid (8, 32) --------------------------
__global__ __launch_bounds__(256) void tc_out(
    const float* __restrict__ bias, float* __restrict__ out)
{
    extern __shared__ char smem[];
    const unsigned sb = smem_u32(smem);
    const int n0 = blockIdx.x * 128, m0 = blockIdx.y * 128;
    const int tid = threadIdx.x, lane = tid & 31, wid = tid >> 5;
    const int wm = wid & 3, wn = wid >> 2;

    float acc[2][8][4] = {};
    gemm_compute(g_oh, g_ol, g_woh, g_wol, m0, n0, sb, tid, acc);

    #pragma unroll
    for (int nt = 0; nt < 8; ++nt) {
        int n = n0 + wn * 64 + nt * 8 + (lane & 3) * 2;
        float b0v = bias[n], b1v = bias[n + 1];
        #pragma unroll
        for (int mt = 0; mt < 2; ++mt) {
            #pragma unroll
            for (int half = 0; half < 2; ++half) {
                int m = m0 + wm * 32 + mt * 16 + (lane >> 2) + 8 * half;
                float2 vv = make_float2(acc[mt][nt][2*half+0] + b0v,
                                        acc[mt][nt][2*half+1] + b1v);
                *(float2*)(out + (size_t)m * D_MODEL + n) = vv;
            }
        }
    }
}

// ---------------- flash attention on HMMA: grid (32, 16, 2), 128 thr -------
// Br=64 q-rows/CTA (warp w owns rows 16w..16w+15), Bc=64 kv-rows/tile.
// SMEM: Qh 8K @0, Ql 8K @8K, 3 KV stages (32KB: kh,kl,vh,vl 8K each) @16K.
// Total 112KB -> 2 CTAs/SM. Row = 64 bf16 = 128B; physchunk = dc ^ (row&7).
#define A_STAGE 32768
#define A_SMEM  (16384 + 3*A_STAGE)

__device__ __forceinline__ void attn_load_stage(
    unsigned st, const __nv_bfloat16* kh, const __nv_bfloat16* kl,
    const __nv_bfloat16* vh, const __nv_bfloat16* vl, size_t base, int tid)
{
    const __nv_bfloat16* srcs[4] = {kh, kl, vh, vl};
    #pragma unroll
    for (int tt = 0; tt < 4; ++tt) {
        const __nv_bfloat16* s = srcs[tt];
        #pragma unroll
        for (int i = 0; i < 4; ++i) {
            int idx = tid + i * 128;         // 0..511 chunks (64 rows x 8)
            int row = idx >> 3, dc = idx & 7;
            unsigned d = st + tt * 8192 + row * 128 + (((dc ^ (row & 7))) << 4);
            cp16(d, s + base + (size_t)row * DK + dc * 8);
        }
    }
}

__global__ __launch_bounds__(128) void attn_mma() {
    extern __shared__ char smem[];
    const unsigned sb = smem_u32(smem);
    const int tid = threadIdx.x, lane = tid & 31, w = tid >> 5;
    const int qt = blockIdx.x, h = blockIdx.y, b = blockIdx.z;

    const size_t headoff = ((size_t)(b * NHEAD + h)) * SEQ * DK;
    const __nv_bfloat16* Qh = g_pqh + headoff + (size_t)qt * 64 * DK;
    const __nv_bfloat16* Ql = g_pql + headoff + (size_t)qt * 64 * DK;
    const __nv_bfloat16* Kh = g_pkh + headoff;
    const __nv_bfloat16* Kl = g_pkl + headoff;
    const __nv_bfloat16* Vh = g_pvh + headoff;
    const __nv_bfloat16* Vl = g_pvl + headoff;

    const unsigned SQH = sb, SQL = sb + 8192, ST0 = sb + 16384;

    attn_load_stage(ST0,           Kh, Kl, Vh, Vl, 0,       tid); CP_COMMIT();
    attn_load_stage(ST0 + A_STAGE, Kh, Kl, Vh, Vl, 64 * DK, tid); CP_COMMIT();

    // load Q tiles (plain LDG/STS, swizzled): 64 rows x 8 chunks per buffer
    #pragma unroll
    for (int tile = 0; tile < 2; ++tile) {
        const __nv_bfloat16* src = tile ? Ql : Qh;
        char* dst = smem + tile * 8192;
        #pragma unroll
        for (int i = 0; i < 4; ++i) {
            int idx = tid + i * 128;
            int row = idx >> 3, dc = idx & 7;
            uint4 v = *(const uint4*)(src + (size_t)row * DK + dc * 8);
            *(uint4*)(dst + row * 128 + (((dc ^ (row & 7))) << 4)) = v;
        }
    }

    float s_m[2] = {-1e30f, -1e30f}, s_l[2] = {0.f, 0.f};
    float o[8][4] = {};

    for (int t = 0; t < 32; ++t) {
        CP_WAIT1();
        __syncthreads();
        if (t + 2 < 32)
            attn_load_stage(ST0 + ((t + 2) % 3) * A_STAGE, Kh, Kl, Vh, Vl,
                            (size_t)(t + 2) * 64 * DK, tid);
        CP_COMMIT();
        const unsigned st = ST0 + (t % 3) * A_STAGE;

        // ---- S = Q K^T (3-term; Q pre-scaled by 0.125*log2e) ----
        float s[8][4] = {};
        #pragma unroll
        for (int ks = 0; ks < 4; ++ks) {
            unsigned qa_h[4], qa_l[4];
            {
                int row = 16 * w + (lane & 15);
                int dc  = 2 * ks + (lane >> 4);
                unsigned off = row * 128 + (((dc ^ (row & 7))) << 4);
                LDSM4(qa_h, SQH + off);
                LDSM4(qa_l, SQL + off);
            }
            #pragma unroll
            for (int q4 = 0; q4 < 4; ++q4) {
                unsigned bh[4], bl[4];
                int krow = q4 * 16 + (lane & 7) + 8 * ((lane >> 4) & 1);
                int kdc  = 2 * ks + ((lane >> 3) & 1);
                unsigned off = krow * 128 + (((kdc ^ (krow & 7))) << 4);
                LDSM4(bh, st + off);
                LDSM4(bl, st + 8192 + off);
                MMA4(s[2*q4],   qa_h, bh[0], bh[1]);
                MMA4(s[2*q4],   qa_h, bl[0], bl[1]);
                MMA4(s[2*q4],   qa_l, bh[0], bh[1]);
                MMA4(s[2*q4+1], qa_h, bh[2], bh[3]);
                MMA4(s[2*q4+1], qa_h, bl[2], bl[3]);
                MMA4(s[2*q4+1], qa_l, bh[2], bh[3]);
            }
        }

        // ---- online softmax (base-2 domain) ----
        #pragma unroll
        for (int r = 0; r < 2; ++r) {
            float mx = -1e30f;
            #pragma unroll
            for (int nt = 0; nt < 8; ++nt)
                mx = fmaxf(mx, fmaxf(s[nt][2*r], s[nt][2*r+1]));
            mx = fmaxf(mx, __shfl_xor_sync(0xffffffffu, mx, 1));
            mx = fmaxf(mx, __shfl_xor_sync(0xffffffffu, mx, 2));
            float mnew  = fmaxf(s_m[r], mx);
            float alpha = fexp2(s_m[r] - mnew);
            float rs = 0.f;
            #pragma unroll
            for (int nt = 0; nt < 8; ++nt) {
                float p0 = fexp2(s[nt][2*r]   - mnew);
                float p1 = fexp2(s[nt][2*r+1] - mnew);
                s[nt][2*r] = p0; s[nt][2*r+1] = p1;
                rs += p0 + p1;
            }
            rs += __shfl_xor_sync(0xffffffffu, rs, 1);
            rs += __shfl_xor_sync(0xffffffffu, rs, 2);
            s_l[r] = s_l[r] * alpha + rs;
            s_m[r] = mnew;
            #pragma unroll
            for (int nt = 0; nt < 8; ++nt) { o[nt][2*r] *= alpha; o[nt][2*r+1] *= alpha; }
        }

        // ---- O += P V (P repacked as A-frags; V via ldmatrix.trans) ----
        #pragma unroll
        for (int ks = 0; ks < 4; ++ks) {
            unsigned pa_h[4], pa_l[4];
            #pragma unroll
            for (int e = 0; e < 4; ++e) {
                int nt = 2 * ks + (e >> 1);
                float x = s[nt][(e & 1) * 2], y = s[nt][(e & 1) * 2 + 1];
                split2(x, y, pa_h[e], pa_l[e]);
            }
            #pragma unroll
            for (int d4 = 0; d4 < 4; ++d4) {
                unsigned vhf[4], vlf[4];
                int vrow = 16 * ks + (lane & 15);
                int vdc  = 2 * d4 + (lane >> 4);
                unsigned off = vrow * 128 + (((vdc ^ (vrow & 7))) << 4);
                LDSM4T(vhf, st + 16384 + off);
                LDSM4T(vlf, st + 24576 + off);
                MMA4(o[2*d4],   pa_h, vhf[0], vhf[1]);
                MMA4(o[2*d4],   pa_h, vlf[0], vlf[1]);
                MMA4(o[2*d4],   pa_l, vhf[0], vhf[1]);
                MMA4(o[2*d4+1], pa_h, vhf[2], vhf[3]);
                MMA4(o[2*d4+1], pa_h, vlf[2], vlf[3]);
                MMA4(o[2*d4+1], pa_l, vhf[2], vhf[3]);
            }
        }
    }

    // ---- epilogue: O/l, split to bf16 h/l at [b][s][h*64+d] ----
    float inv[2] = {1.f / s_l[0], 1.f / s_l[1]};
    #pragma unroll
    for (int nt = 0; nt < 8; ++nt) {
        int d = h * DK + nt * 8 + (lane & 3) * 2;
        #pragma unroll
        for (int r = 0; r < 2; ++r) {
            int srow = qt * 64 + 16 * w + (lane >> 2) + 8 * r;
            float x = o[nt][2*r] * inv[r], y = o[nt][2*r+1] * inv[r];
            unsigned hi, lo; split2(x, y, hi, lo);
            size_t dst = (size_t)(b * SEQ + srow) * D_MODEL + d;
            *(unsigned*)(g_oh + dst) = hi;
            *(unsigned*)(g_ol + dst) = lo;
        }
    }
}

// ---------------- launcher --------------------------------------------------
extern "C" void kernel_launch(void* const* d_in, const int* in_sizes, int n_in,
                              void* d_out, int out_size) {
    const float* query = (const float*)d_in[0];
    const float* key   = (const float*)d_in[1];
    const float* value = (const float*)d_in[2];
    const float* Wq    = (const float*)d_in[3];
    const float* bq    = (const float*)d_in[4];
    const float* Wk    = (const float*)d_in[5];
    const float* bk    = (const float*)d_in[6];
    const float* Wv    = (const float*)d_in[7];
    const float* bv    = (const float*)d_in[8];
    const float* Wo    = (const float*)d_in[9];
    const float* bo    = (const float*)d_in[10];
    float* out = (float*)d_out;

    cudaFuncSetAttribute(tc_qkv,   cudaFuncAttributeMaxDynamicSharedMemorySize, G_SMEM);
    cudaFuncSetAttribute(tc_out,   cudaFuncAttributeMaxDynamicSharedMemorySize, G_SMEM);
    cudaFuncSetAttribute(attn_mma, cudaFuncAttributeMaxDynamicSharedMemorySize, A_SMEM);

    dim3 gS(592, 7);
    split_all<<<gS, 256>>>(query, key, value, Wq, Wk, Wv, Wo);

    dim3 gQKV(D_MODEL / 128, MTOT / 128, 3);   // (8, 32, 3)
    tc_qkv<<<gQKV, 256, G_SMEM>>>(bq, bk, bv);

    dim3 gAtt(SEQ / 64, NHEAD, BATCH);         // (32, 16, 2)
    attn_mma<<<gAtt, 128, A_SMEM>>>();

    dim3 gOut(D_MODEL / 128, MTOT / 128, 1);   // (8, 32)
    tc_out<<<gOut, 256, G_SMEM>>>(bo, out);
}

// round 8
// speedup vs baseline: 3.2342x; 1.0361x over previous
#include <cuda_runtime.h>
#include <cuda_bf16.h>
#include <stdint.h>

#define D_MODEL 1024
#define NHEAD   16
#define DK      64
#define BATCH   2
#define SEQ     2048
#define MTOT    (BATCH*SEQ)   // 4096

// ---------------- scratch (static device globals; no allocations) ----------
__device__ __nv_bfloat16 g_qh[(size_t)MTOT*D_MODEL],    g_ql[(size_t)MTOT*D_MODEL];
__device__ __nv_bfloat16 g_kh[(size_t)MTOT*D_MODEL],    g_kl[(size_t)MTOT*D_MODEL];
__device__ __nv_bfloat16 g_vh[(size_t)MTOT*D_MODEL],    g_vl[(size_t)MTOT*D_MODEL];
__device__ __nv_bfloat16 g_wqh[(size_t)D_MODEL*D_MODEL], g_wql[(size_t)D_MODEL*D_MODEL];
__device__ __nv_bfloat16 g_wkh[(size_t)D_MODEL*D_MODEL], g_wkl[(size_t)D_MODEL*D_MODEL];
__device__ __nv_bfloat16 g_wvh[(size_t)D_MODEL*D_MODEL], g_wvl[(size_t)D_MODEL*D_MODEL];
__device__ __nv_bfloat16 g_woh[(size_t)D_MODEL*D_MODEL], g_wol[(size_t)D_MODEL*D_MODEL];
// projected Q/K/V splits, head-major [b][h][s][d]  (Q pre-scaled by 0.125*log2e)
__device__ __nv_bfloat16 g_pqh[(size_t)MTOT*D_MODEL],   g_pql[(size_t)MTOT*D_MODEL];
__device__ __nv_bfloat16 g_pkh[(size_t)MTOT*D_MODEL],   g_pkl[(size_t)MTOT*D_MODEL];
__device__ __nv_bfloat16 g_pvh[(size_t)MTOT*D_MODEL],   g_pvl[(size_t)MTOT*D_MODEL];
// attention output splits [b][s][h*64+d]
__device__ __nv_bfloat16 g_oh[(size_t)MTOT*D_MODEL],    g_ol[(size_t)MTOT*D_MODEL];

// ======================= low-level helpers (base ISA only) ================
__device__ __forceinline__ unsigned smem_u32(const void* p) {
    unsigned a;
    asm("{ .reg .u64 t; cvta.to.shared.u64 t, %1; cvt.u32.u64 %0, t; }" : "=r"(a) : "l"(p));
    return a;
}
__device__ __forceinline__ void cp16(unsigned dst, const void* src) {
    asm volatile("cp.async.cg.shared.global [%0], [%1], 16;" :: "r"(dst), "l"(src));
}
#define CP_COMMIT() asm volatile("cp.async.commit_group;" ::: "memory")
#define CP_WAIT1()  asm volatile("cp.async.wait_group 1;"  ::: "memory")
#define CP_WAIT0()  asm volatile("cp.async.wait_group 0;"  ::: "memory")

#define LDSM4(r, a) \
    asm volatile("ldmatrix.sync.aligned.m8n8.x4.shared.b16 {%0,%1,%2,%3}, [%4];" \
        : "=r"((r)[0]), "=r"((r)[1]), "=r"((r)[2]), "=r"((r)[3]) : "r"(a))
#define LDSM4T(r, a) \
    asm volatile("ldmatrix.sync.aligned.m8n8.x4.trans.shared.b16 {%0,%1,%2,%3}, [%4];" \
        : "=r"((r)[0]), "=r"((r)[1]), "=r"((r)[2]), "=r"((r)[3]) : "r"(a))

#define MMA4(d, a, b0, b1) \
    asm volatile("mma.sync.aligned.m16n8k16.row.col.f32.bf16.bf16.f32 " \
        "{%0,%1,%2,%3}, {%4,%5,%6,%7}, {%8,%9}, {%0,%1,%2,%3};" \
        : "+f"((d)[0]), "+f"((d)[1]), "+f"((d)[2]), "+f"((d)[3]) \
        : "r"((a)[0]), "r"((a)[1]), "r"((a)[2]), "r"((a)[3]), "r"(b0), "r"(b1))

__device__ __forceinline__ float fexp2(float x) {
    float y; asm("ex2.approx.f32 %0, %1;" : "=f"(y) : "f"(x)); return y;
}
__device__ __forceinline__ void split2(float x, float y, unsigned& hi, unsigned& lo) {
    __nv_bfloat162 h = __float22bfloat162_rn(make_float2(x, y));
    float2 hf = __bfloat1622float2(h);
    __nv_bfloat162 l = __float22bfloat162_rn(make_float2(x - hf.x, y - hf.y));
    hi = *(unsigned*)&h; lo = *(unsigned*)&l;
}

// ======================= split kernel: fp32 -> bf16 hi/lo ===================
__global__ __launch_bounds__(256) void split_all(
    const float* q, const float* k, const float* v,
    const float* wq, const float* wk, const float* wv, const float* wo)
{
    const int z = blockIdx.y;
    const float* src; __nv_bfloat16 *dh, *dl; int n4;
    const int NA = MTOT*D_MODEL/4, NW = D_MODEL*D_MODEL/4;
    switch (z) {
        case 0: src = q;  dh = g_qh;  dl = g_ql;  n4 = NA; break;
        case 1: src = k;  dh = g_kh;  dl = g_kl;  n4 = NA; break;
        case 2: src = v;  dh = g_vh;  dl = g_vl;  n4 = NA; break;
        case 3: src = wq; dh = g_wqh; dl = g_wql; n4 = NW; break;
        case 4: src = wk; dh = g_wkh; dl = g_wkl; n4 = NW; break;
        case 5: src = wv; dh = g_wvh; dl = g_wvl; n4 = NW; break;
        default:src = wo; dh = g_woh; dl = g_wol; n4 = NW; break;
    }
    for (int i = blockIdx.x * blockDim.x + threadIdx.x; i < n4; i += gridDim.x * blockDim.x) {
        float4 vv = ((const float4*)src)[i];
        unsigned h0, l0, h1, l1;
        split2(vv.x, vv.y, h0, l0);
        split2(vv.z, vv.w, h1, l1);
        ((unsigned*)dh)[2*i] = h0; ((unsigned*)dh)[2*i+1] = h1;
        ((unsigned*)dl)[2*i] = l0; ((unsigned*)dl)[2*i+1] = l1;
    }
}

// ======================= HMMA GEMM core (3-term bf16 split) ================
// BM=BN=128, BK=32, 256 thr (8 warps = 4x2), warp tile 32x64, 3 stages.
#define G_STAGE 32768
#define G_SMEM  (3*G_STAGE)

__device__ __forceinline__ void gemm_load_stage(
    unsigned st, const __nv_bfloat16* Ah, const __nv_bfloat16* Al,
    const __nv_bfloat16* Bh, const __nv_bfloat16* Bl,
    int m0, int n0, int k0, int tid)
{
    const __nv_bfloat16* srcs[4] = {Ah, Al, Bh, Bl};
    #pragma unroll
    for (int tt = 0; tt < 4; ++tt) {
        const int r0 = (tt < 2) ? m0 : n0;
        const __nv_bfloat16* s = srcs[tt];
        #pragma unroll
        for (int i = 0; i < 2; ++i) {
            int idx = tid + i * 256;
            int row = idx >> 2, kc = idx & 3;
            unsigned d = st + tt * 8192 + row * 64 + (((kc ^ ((row >> 1) & 3))) << 4);
            cp16(d, s + (size_t)(r0 + row) * D_MODEL + k0 + kc * 8);
        }
    }
}

__device__ __forceinline__ void gemm_compute(
    const __nv_bfloat16* Ah, const __nv_bfloat16* Al,
    const __nv_bfloat16* Bh, const __nv_bfloat16* Bl,
    int m0, int n0, unsigned sb, int tid, float acc[2][8][4])
{
    const int lane = tid & 31, wid = tid >> 5;
    const int wm = wid & 3, wn = wid >> 2;

    gemm_load_stage(sb,            Ah, Al, Bh, Bl, m0, n0, 0,  tid); CP_COMMIT();
    gemm_load_stage(sb + G_STAGE,  Ah, Al, Bh, Bl, m0, n0, 32, tid); CP_COMMIT();

    for (int it = 0; it < 32; ++it) {
        CP_WAIT1();
        __syncthreads();
        if (it + 2 < 32)
            gemm_load_stage(sb + ((it + 2) % 3) * G_STAGE, Ah, Al, Bh, Bl,
                            m0, n0, (it + 2) * 32, tid);
        CP_COMMIT();
        const unsigned st = sb + (it % 3) * G_STAGE;
        #pragma unroll
        for (int ks = 0; ks < 2; ++ks) {
            unsigned aH[2][4], aL[2][4];
            #pragma unroll
            for (int mt = 0; mt < 2; ++mt) {
                int row = wm * 32 + mt * 16 + (lane & 15);
                int kc  = 2 * ks + (lane >> 4);
                unsigned off = row * 64 + (((kc ^ ((row >> 1) & 3))) << 4);
                LDSM4(aH[mt], st + off);
                LDSM4(aL[mt], st + 8192 + off);
            }
            #pragma unroll
            for (int q = 0; q < 4; ++q) {
                unsigned bH[4], bL[4];
                int row = wn * 64 + q * 16 + (lane & 7) + 8 * ((lane >> 4) & 1);
                int kc  = 2 * ks + ((lane >> 3) & 1);
                unsigned off = row * 64 + (((kc ^ ((row >> 1) & 3))) << 4);
                LDSM4(bH, st + 16384 + off);
                LDSM4(bL, st + 24576 + off);
                #pragma unroll
                for (int mt = 0; mt < 2; ++mt) {
                    MMA4(acc[mt][2*q],   aH[mt], bH[0], bH[1]);
                    MMA4(acc[mt][2*q],   aH[mt], bL[0], bL[1]);
                    MMA4(acc[mt][2*q],   aL[mt], bH[0], bH[1]);
                    MMA4(acc[mt][2*q+1], aH[mt], bH[2], bH[3]);
                    MMA4(acc[mt][2*q+1], aH[mt], bL[2], bL[3]);
                    MMA4(acc[mt][2*q+1], aL[mt], bH[2], bH[3]);
                }
            }
        }
    }
}

// ---------------- QKV projection: grid (8, 32, 3) --------------------------
__global__ __launch_bounds__(256) void tc_qkv(
    const float* __restrict__ bq, const float* __restrict__ bk,
    const float* __restrict__ bv)
{
    extern __shared__ char smem[];
    const unsigned sb = smem_u32(smem);
    const int z = blockIdx.z;
    const __nv_bfloat16 *Ah, *Al, *Bh, *Bl;
    __nv_bfloat16 *dh, *dl;
    const float* bias;
    float scale;
    if (z == 0)      { Ah=g_qh; Al=g_ql; Bh=g_wqh; Bl=g_wql; dh=g_pqh; dl=g_pql; bias=bq; scale=0.18033688f; }
    else if (z == 1) { Ah=g_kh; Al=g_kl; Bh=g_wkh; Bl=g_wkl; dh=g_pkh; dl=g_pkl; bias=bk; scale=1.0f; }
    else             { Ah=g_vh; Al=g_vl; Bh=g_wvh; Bl=g_wvl; dh=g_pvh; dl=g_pvl; bias=bv; scale=1.0f; }

    const int n0 = blockIdx.x * 128, m0 = blockIdx.y * 128;
    const int tid = threadIdx.x, lane = tid & 31, wid = tid >> 5;
    const int wm = wid & 3, wn = wid >> 2;

    float acc[2][8][4] = {};
    gemm_compute(Ah, Al, Bh, Bl, m0, n0, sb, tid, acc);

    #pragma unroll
    for (int nt = 0; nt < 8; ++nt) {
        int n = n0 + wn * 64 + nt * 8 + (lane & 3) * 2;
        float b0v = bias[n], b1v = bias[n + 1];
        int hd = n >> 6, d = n & 63;
        #pragma unroll
        for (int mt = 0; mt < 2; ++mt) {
            #pragma unroll
            for (int half = 0; half < 2; ++half) {
                int m = m0 + wm * 32 + mt * 16 + (lane >> 2) + 8 * half;
                float x = (acc[mt][nt][2*half+0] + b0v) * scale;
                float y = (acc[mt][nt][2*half+1] + b1v) * scale;
                unsigned hi, lo; split2(x, y, hi, lo);
                size_t dst = ((size_t)((m >> 11) * NHEAD + hd) * SEQ + (m & (SEQ-1))) * DK + d;
                *(unsigned*)(dh + dst) = hi;
                *(unsigned*)(dl + dst) = lo;
            }
        }
    }
}

// ---------------- output projection: grid (8, 32) --------------------------
__global__ __launch_bounds__(256) void tc_out(
    const float* __restrict__ bias, float* __restrict__ out)
{
    extern __shared__ char smem[];
    const unsigned sb = smem_u32(smem);
    const int n0 = blockIdx.x * 128, m0 = blockIdx.y * 128;
    const int tid = threadIdx.x, lane = tid & 31, wid = tid >> 5;
    const int wm = wid & 3, wn = wid >> 2;

    float acc[2][8][4] = {};
    gemm_compute(g_oh, g_ol, g_woh, g_wol, m0, n0, sb, tid, acc);

    #pragma unroll
    for (int nt = 0; nt < 8; ++nt) {
        int n = n0 + wn * 64 + nt * 8 + (lane & 3) * 2;
        float b0v = bias[n], b1v = bias[n + 1];
        #pragma unroll
        for (int mt = 0; mt < 2; ++mt) {
            #pragma unroll
            for (int half = 0; half < 2; ++half) {
                int m = m0 + wm * 32 + mt * 16 + (lane >> 2) + 8 * half;
                float2 vv = make_float2(acc[mt][nt][2*half+0] + b0v,
                                        acc[mt][nt][2*half+1] + b1v);
                *(float2*)(out + (size_t)m * D_MODEL + n) = vv;
            }
        }
    }
}

// ---------------- flash attention on HMMA: grid (32, 16, 2), 128 thr -------
// Br=64 (warp w owns rows 16w..16w+15), Bc=32 kv-rows/tile, 64 tiles.
// Q fragments live in REGISTERS (loaded once via stage-0 smem).
// SMEM: 3 KV stages x 16KB (kh@0,kl@4K,vh@8K,vl@12K per stage) = 48KB
// -> 3 CTAs/SM (launch_bounds(128,3)). Row = 64 bf16 = 128B; chunk swizzle
// physchunk = dc ^ (row&7).
#define A_STAGE 16384
#define A_SMEM  (3*A_STAGE)

__device__ __forceinline__ void attn_load_stage(
    unsigned st, const __nv_bfloat16* kh, const __nv_bfloat16* kl,
    const __nv_bfloat16* vh, const __nv_bfloat16* vl, size_t base, int tid)
{
    const __nv_bfloat16* srcs[4] = {kh, kl, vh, vl};
    #pragma unroll
    for (int tt = 0; tt < 4; ++tt) {
        const __nv_bfloat16* s = srcs[tt];
        #pragma unroll
        for (int i = 0; i < 2; ++i) {
            int idx = tid + i * 128;         // 0..255 chunks (32 rows x 8)
            int row = idx >> 3, dc = idx & 7;
            unsigned d = st + tt * 4096 + row * 128 + (((dc ^ (row & 7))) << 4);
            cp16(d, s + base + (size_t)row * DK + dc * 8);
        }
    }
}

__global__ void __launch_bounds__(128, 3) attn_mma() {
    extern __shared__ char smem[];
    const unsigned sb = smem_u32(smem);
    const int tid = threadIdx.x, lane = tid & 31, w = tid >> 5;
    const int qt = blockIdx.x, h = blockIdx.y, b = blockIdx.z;

    const size_t headoff = ((size_t)(b * NHEAD + h)) * SEQ * DK;
    const __nv_bfloat16* Qhp = g_pqh + headoff + (size_t)qt * 64 * DK;
    const __nv_bfloat16* Qlp = g_pql + headoff + (size_t)qt * 64 * DK;
    const __nv_bfloat16* Kh = g_pkh + headoff;
    const __nv_bfloat16* Kl = g_pkl + headoff;
    const __nv_bfloat16* Vh = g_pvh + headoff;
    const __nv_bfloat16* Vl = g_pvl + headoff;

    // ---- prologue: stage Q through smem stage-0, park fragments in regs ----
    {
        const __nv_bfloat16* qsrc[2] = {Qhp, Qlp};
        #pragma unroll
        for (int tile = 0; tile < 2; ++tile)
            #pragma unroll
            for (int i = 0; i < 4; ++i) {
                int idx = tid + i * 128;     // 0..511 (64 rows x 8)
                int row = idx >> 3, dc = idx & 7;
                cp16(sb + tile * 8192 + row * 128 + (((dc ^ (row & 7))) << 4),
                     qsrc[tile] + (size_t)row * DK + dc * 8);
            }
        CP_COMMIT(); CP_WAIT0();
        __syncthreads();
    }
    unsigned qh_f[4][4], ql_f[4][4];
    #pragma unroll
    for (int ks = 0; ks < 4; ++ks) {
        int row = 16 * w + (lane & 15);
        int dc  = 2 * ks + (lane >> 4);
        unsigned off = row * 128 + (((dc ^ (row & 7))) << 4);
        LDSM4(qh_f[ks], sb + off);
        LDSM4(ql_f[ks], sb + 8192 + off);
    }
    __syncthreads();   // everyone done with stage-0 before KV pipeline reuses it

    attn_load_stage(sb,           Kh, Kl, Vh, Vl, 0,       tid); CP_COMMIT();
    attn_load_stage(sb + A_STAGE, Kh, Kl, Vh, Vl, 32 * DK, tid); CP_COMMIT();

    float s_m[2] = {-1e30f, -1e30f}, s_l[2] = {0.f, 0.f};
    float o[8][4] = {};

    for (int t = 0; t < 64; ++t) {
        CP_WAIT1();
        __syncthreads();
        if (t + 2 < 64)
            attn_load_stage(sb + ((t + 2) % 3) * A_STAGE, Kh, Kl, Vh, Vl,
                            (size_t)(t + 2) * 32 * DK, tid);
        CP_COMMIT();
        const unsigned st = sb + (t % 3) * A_STAGE;

        // ---- S = Q K^T (3-term; Q pre-scaled by 0.125*log2e) ----
        float s[4][4] = {};
        #pragma unroll
        for (int ks = 0; ks < 4; ++ks) {
            #pragma unroll
            for (int q4 = 0; q4 < 2; ++q4) {
                unsigned bh[4], bl[4];
                int krow = q4 * 16 + (lane & 7) + 8 * ((lane >> 4) & 1);
                int kdc  = 2 * ks + ((lane >> 3) & 1);
                unsigned off = krow * 128 + (((kdc ^ (krow & 7))) << 4);
                LDSM4(bh, st + off);
                LDSM4(bl, st + 4096 + off);
                MMA4(s[2*q4],   qh_f[ks], bh[0], bh[1]);
                MMA4(s[2*q4],   qh_f[ks], bl[0], bl[1]);
                MMA4(s[2*q4],   ql_f[ks], bh[0], bh[1]);
                MMA4(s[2*q4+1], qh_f[ks], bh[2], bh[3]);
                MMA4(s[2*q4+1], qh_f[ks], bl[2], bl[3]);
                MMA4(s[2*q4+1], ql_f[ks], bh[2], bh[3]);
            }
        }

        // ---- online softmax (base-2 domain) ----
        #pragma unroll
        for (int r = 0; r < 2; ++r) {
            float mx = -1e30f;
            #pragma unroll
            for (int nt = 0; nt < 4; ++nt)
                mx = fmaxf(mx, fmaxf(s[nt][2*r], s[nt][2*r+1]));
            mx = fmaxf(mx, __shfl_xor_sync(0xffffffffu, mx, 1));
            mx = fmaxf(mx, __shfl_xor_sync(0xffffffffu, mx, 2));
            float mnew  = fmaxf(s_m[r], mx);
            float alpha = fexp2(s_m[r] - mnew);
            float rs = 0.f;
            #pragma unroll
            for (int nt = 0; nt < 4; ++nt) {
                float p0 = fexp2(s[nt][2*r]   - mnew);
                float p1 = fexp2(s[nt][2*r+1] - mnew);
                s[nt][2*r] = p0; s[nt][2*r+1] = p1;
                rs += p0 + p1;
            }
            rs += __shfl_xor_sync(0xffffffffu, rs, 1);
            rs += __shfl_xor_sync(0xffffffffu, rs, 2);
            s_l[r] = s_l[r] * alpha + rs;
            s_m[r] = mnew;
            #pragma unroll
            for (int nt = 0; nt < 8; ++nt) { o[nt][2*r] *= alpha; o[nt][2*r+1] *= alpha; }
        }

        // ---- O += P V (P repacked as A-frags; V via ldmatrix.trans) ----
        #pragma unroll
        for (int ks = 0; ks < 2; ++ks) {
            unsigned pa_h[4], pa_l[4];
            #pragma unroll
            for (int e = 0; e < 4; ++e) {
                int nt = 2 * ks + (e >> 1);
                float x = s[nt][(e & 1) * 2], y = s[nt][(e & 1) * 2 + 1];
                split2(x, y, pa_h[e], pa_l[e]);
            }
            #pragma unroll
            for (int d4 = 0; d4 < 4; ++d4) {
                unsigned vhf[4], vlf[4];
                int vrow = 16 * ks + (lane & 15);
                int vdc  = 2 * d4 + (lane >> 4);
                unsigned off = vrow * 128 + (((vdc ^ (vrow & 7))) << 4);
                LDSM4T(vhf, st + 8192  + off);
                LDSM4T(vlf, st + 12288 + off);
                MMA4(o[2*d4],   pa_h, vhf[0], vhf[1]);
                MMA4(o[2*d4],   pa_h, vlf[0], vlf[1]);
                MMA4(o[2*d4],   pa_l, vhf[0], vhf[1]);
                MMA4(o[2*d4+1], pa_h, vhf[2], vhf[3]);
                MMA4(o[2*d4+1], pa_h, vlf[2], vlf[3]);
                MMA4(o[2*d4+1], pa_l, vhf[2], vhf[3]);
            }
        }
    }

    // ---- epilogue: O/l, split to bf16 h/l at [b][s][h*64+d] ----
    float inv[2] = {1.f / s_l[0], 1.f / s_l[1]};
    #pragma unroll
    for (int nt = 0; nt < 8; ++nt) {
        int d = h * DK + nt * 8 + (lane & 3) * 2;
        #pragma unroll
        for (int r = 0; r < 2; ++r) {
            int srow = qt * 64 + 16 * w + (lane >> 2) + 8 * r;
            float x = o[nt][2*r] * inv[r], y = o[nt][2*r+1] * inv[r];
            unsigned hi, lo; split2(x, y, hi, lo);
            size_t dst = (size_t)(b * SEQ + srow) * D_MODEL + d;
            *(unsigned*)(g_oh + dst) = hi;
            *(unsigned*)(g_ol + dst) = lo;
        }
    }
}

// ---------------- launcher --------------------------------------------------
extern "C" void kernel_launch(void* const* d_in, const int* in_sizes, int n_in,
                              void* d_out, int out_size) {
    const float* query = (const float*)d_in[0];
    const float* key   = (const float*)d_in[1];
    const float* value = (const float*)d_in[2];
    const float* Wq    = (const float*)d_in[3];
    const float* bq    = (const float*)d_in[4];
    const float* Wk    = (const float*)d_in[5];
    const float* bk    = (const float*)d_in[6];
    const float* Wv    = (const float*)d_in[7];
    const float* bv    = (const float*)d_in[8];
    const float* Wo    = (const float*)d_in[9];
    const float* bo    = (const float*)d_in[10];
    float* out = (float*)d_out;

    cudaFuncSetAttribute(tc_qkv,   cudaFuncAttributeMaxDynamicSharedMemorySize, G_SMEM);
    cudaFuncSetAttribute(tc_out,   cudaFuncAttributeMaxDynamicSharedMemorySize, G_SMEM);
    cudaFuncSetAttribute(attn_mma, cudaFuncAttributeMaxDynamicSharedMemorySize, A_SMEM);

    dim3 gS(592, 7);
    split_all<<<gS, 256>>>(query, key, value, Wq, Wk, Wv, Wo);

    dim3 gQKV(D_MODEL / 128, MTOT / 128, 3);   // (8, 32, 3)
    tc_qkv<<<gQKV, 256, G_SMEM>>>(bq, bk, bv);

    dim3 gAtt(SEQ / 64, NHEAD, BATCH);         // (32, 16, 2)
    attn_mma<<<gAtt, 128, A_SMEM>>>();

    dim3 gOut(D_MODEL / 128, MTOT / 128, 1);   // (8, 32)
    tc_out<<<gOut, 256, G_SMEM>>>(bo, out);
}

// round 9
// speedup vs baseline: 3.2398x; 1.0017x over previous
#include <cuda_runtime.h>
#include <cuda_bf16.h>
#include <stdint.h>

#define D_MODEL 1024
#define NHEAD   16
#define DK      64
#define BATCH   2
#define SEQ     2048
#define MTOT    (BATCH*SEQ)   // 4096
#define NELEM   ((size_t)MTOT*D_MODEL)

// ---------------- scratch (static device globals; no allocations) ----------
__device__ __nv_bfloat16 g_qh[NELEM],    g_ql[NELEM];
__device__ __nv_bfloat16 g_kh[NELEM],    g_kl[NELEM];
__device__ __nv_bfloat16 g_vh[NELEM],    g_vl[NELEM];
__device__ __nv_bfloat16 g_wqh[(size_t)D_MODEL*D_MODEL], g_wql[(size_t)D_MODEL*D_MODEL];
__device__ __nv_bfloat16 g_wkh[(size_t)D_MODEL*D_MODEL], g_wkl[(size_t)D_MODEL*D_MODEL];
__device__ __nv_bfloat16 g_wvh[(size_t)D_MODEL*D_MODEL], g_wvl[(size_t)D_MODEL*D_MODEL];
__device__ __nv_bfloat16 g_woh[(size_t)D_MODEL*D_MODEL], g_wol[(size_t)D_MODEL*D_MODEL];
// projected tensors, head-major [b][h][s][d]; merged arrays (fewer base regs)
__device__ __nv_bfloat16 g_pq [2][NELEM];          // Q hi/lo (pre-scaled 0.125*log2e)
__device__ __nv_bfloat16 g_pkv[4][NELEM];          // Kh, Kl, Vh, Vl
__device__ __nv_bfloat16 g_po [2][NELEM];          // attn out hi/lo [b][s][h*64+d]

// ======================= low-level helpers (base ISA only) ================
__device__ __forceinline__ unsigned smem_u32(const void* p) {
    unsigned a;
    asm("{ .reg .u64 t; cvta.to.shared.u64 t, %1; cvt.u32.u64 %0, t; }" : "=r"(a) : "l"(p));
    return a;
}
__device__ __forceinline__ void cp16(unsigned dst, const void* src) {
    asm volatile("cp.async.cg.shared.global [%0], [%1], 16;" :: "r"(dst), "l"(src));
}
#define CP_COMMIT() asm volatile("cp.async.commit_group;" ::: "memory")
#define CP_WAIT1()  asm volatile("cp.async.wait_group 1;"  ::: "memory")
#define CP_WAIT0()  asm volatile("cp.async.wait_group 0;"  ::: "memory")

#define LDSM4(r, a) \
    asm volatile("ldmatrix.sync.aligned.m8n8.x4.shared.b16 {%0,%1,%2,%3}, [%4];" \
        : "=r"((r)[0]), "=r"((r)[1]), "=r"((r)[2]), "=r"((r)[3]) : "r"(a))
#define LDSM4T(r, a) \
    asm volatile("ldmatrix.sync.aligned.m8n8.x4.trans.shared.b16 {%0,%1,%2,%3}, [%4];" \
        : "=r"((r)[0]), "=r"((r)[1]), "=r"((r)[2]), "=r"((r)[3]) : "r"(a))

#define MMA4(d, a, b0, b1) \
    asm volatile("mma.sync.aligned.m16n8k16.row.col.f32.bf16.bf16.f32 " \
        "{%0,%1,%2,%3}, {%4,%5,%6,%7}, {%8,%9}, {%0,%1,%2,%3};" \
        : "+f"((d)[0]), "+f"((d)[1]), "+f"((d)[2]), "+f"((d)[3]) \
        : "r"((a)[0]), "r"((a)[1]), "r"((a)[2]), "r"((a)[3]), "r"(b0), "r"(b1))

__device__ __forceinline__ float fexp2(float x) {
    float y; asm("ex2.approx.f32 %0, %1;" : "=f"(y) : "f"(x)); return y;
}
__device__ __forceinline__ void split2(float x, float y, unsigned& hi, unsigned& lo) {
    __nv_bfloat162 h = __float22bfloat162_rn(make_float2(x, y));
    float2 hf = __bfloat1622float2(h);
    __nv_bfloat162 l = __float22bfloat162_rn(make_float2(x - hf.x, y - hf.y));
    hi = *(unsigned*)&h; lo = *(unsigned*)&l;
}

// ======================= split kernel: fp32 -> bf16 hi/lo ===================
__global__ __launch_bounds__(256) void split_all(
    const float* q, const float* k, const float* v,
    const float* wq, const float* wk, const float* wv, const float* wo)
{
    const int z = blockIdx.y;
    const float* src; __nv_bfloat16 *dh, *dl; int n4;
    const int NA = MTOT*D_MODEL/4, NW = D_MODEL*D_MODEL/4;
    switch (z) {
        case 0: src = q;  dh = g_qh;  dl = g_ql;  n4 = NA; break;
        case 1: src = k;  dh = g_kh;  dl = g_kl;  n4 = NA; break;
        case 2: src = v;  dh = g_vh;  dl = g_vl;  n4 = NA; break;
        case 3: src = wq; dh = g_wqh; dl = g_wql; n4 = NW; break;
        case 4: src = wk; dh = g_wkh; dl = g_wkl; n4 = NW; break;
        case 5: src = wv; dh = g_wvh; dl = g_wvl; n4 = NW; break;
        default:src = wo; dh = g_woh; dl = g_wol; n4 = NW; break;
    }
    for (int i = blockIdx.x * blockDim.x + threadIdx.x; i < n4; i += gridDim.x * blockDim.x) {
        float4 vv = ((const float4*)src)[i];
        unsigned h0, l0, h1, l1;
        split2(vv.x, vv.y, h0, l0);
        split2(vv.z, vv.w, h1, l1);
        ((unsigned*)dh)[2*i] = h0; ((unsigned*)dh)[2*i+1] = h1;
        ((unsigned*)dl)[2*i] = l0; ((unsigned*)dl)[2*i+1] = l1;
    }
}

// ======================= HMMA GEMM core (3-term bf16 split) ================
// BM=BN=128, BK=32, 256 thr (8 warps = 4x2), warp tile 32x64, 3 stages.
#define G_STAGE 32768
#define G_SMEM  (3*G_STAGE)

__device__ __forceinline__ void gemm_load_stage(
    unsigned st, const __nv_bfloat16* Ah, const __nv_bfloat16* Al,
    const __nv_bfloat16* Bh, const __nv_bfloat16* Bl,
    int m0, int n0, int k0, int tid)
{
    const __nv_bfloat16* srcs[4] = {Ah, Al, Bh, Bl};
    #pragma unroll
    for (int tt = 0; tt < 4; ++tt) {
        const int r0 = (tt < 2) ? m0 : n0;
        const __nv_bfloat16* s = srcs[tt];
        #pragma unroll
        for (int i = 0; i < 2; ++i) {
            int idx = tid + i * 256;
            int row = idx >> 2, kc = idx & 3;
            unsigned d = st + tt * 8192 + row * 64 + (((kc ^ ((row >> 1) & 3))) << 4);
            cp16(d, s + (size_t)(r0 + row) * D_MODEL + k0 + kc * 8);
        }
    }
}

__device__ __forceinline__ void gemm_compute(
    const __nv_bfloat16* Ah, const __nv_bfloat16* Al,
    const __nv_bfloat16* Bh, const __nv_bfloat16* Bl,
    int m0, int n0, unsigned sb, int tid, float acc[2][8][4])
{
    const int lane = tid & 31, wid = tid >> 5;
    const int wm = wid & 3, wn = wid >> 2;

    gemm_load_stage(sb,            Ah, Al, Bh, Bl, m0, n0, 0,  tid); CP_COMMIT();
    gemm_load_stage(sb + G_STAGE,  Ah, Al, Bh, Bl, m0, n0, 32, tid); CP_COMMIT();

    for (int it = 0; it < 32; ++it) {
        CP_WAIT1();
        __syncthreads();
        if (it + 2 < 32)
            gemm_load_stage(sb + ((it + 2) % 3) * G_STAGE, Ah, Al, Bh, Bl,
                            m0, n0, (it + 2) * 32, tid);
        CP_COMMIT();
        const unsigned st = sb + (it % 3) * G_STAGE;
        #pragma unroll
        for (int ks = 0; ks < 2; ++ks) {
            unsigned aH[2][4], aL[2][4];
            #pragma unroll
            for (int mt = 0; mt < 2; ++mt) {
                int row = wm * 32 + mt * 16 + (lane & 15);
                int kc  = 2 * ks + (lane >> 4);
                unsigned off = row * 64 + (((kc ^ ((row >> 1) & 3))) << 4);
                LDSM4(aH[mt], st + off);
                LDSM4(aL[mt], st + 8192 + off);
            }
            #pragma unroll
            for (int q = 0; q < 4; ++q) {
                unsigned bH[4], bL[4];
                int row = wn * 64 + q * 16 + (lane & 7) + 8 * ((lane >> 4) & 1);
                int kc  = 2 * ks + ((lane >> 3) & 1);
                unsigned off = row * 64 + (((kc ^ ((row >> 1) & 3))) << 4);
                LDSM4(bH, st + 16384 + off);
                LDSM4(bL, st + 24576 + off);
                #pragma unroll
                for (int mt = 0; mt < 2; ++mt) {
                    MMA4(acc[mt][2*q],   aH[mt], bH[0], bH[1]);
                    MMA4(acc[mt][2*q],   aH[mt], bL[0], bL[1]);
                    MMA4(acc[mt][2*q],   aL[mt], bH[0], bH[1]);
                    MMA4(acc[mt][2*q+1], aH[mt], bH[2], bH[3]);
                    MMA4(acc[mt][2*q+1], aH[mt], bL[2], bL[3]);
                    MMA4(acc[mt][2*q+1], aL[mt], bH[2], bH[3]);
                }
            }
        }
    }
}

// ---------------- QKV projection: grid (8, 32, 3) --------------------------
__global__ __launch_bounds__(256) void tc_qkv(
    const float* __restrict__ bq, const float* __restrict__ bk,
    const float* __restrict__ bv)
{
    extern __shared__ char smem[];
    const unsigned sb = smem_u32(smem);
    const int z = blockIdx.z;
    const __nv_bfloat16 *Ah, *Al, *Bh, *Bl;
    __nv_bfloat16 *dh, *dl;
    const float* bias;
    float scale;
    if (z == 0)      { Ah=g_qh; Al=g_ql; Bh=g_wqh; Bl=g_wql; dh=g_pq[0];  dl=g_pq[1];  bias=bq; scale=0.18033688f; }
    else if (z == 1) { Ah=g_kh; Al=g_kl; Bh=g_wkh; Bl=g_wkl; dh=g_pkv[0]; dl=g_pkv[1]; bias=bk; scale=1.0f; }
    else             { Ah=g_vh; Al=g_vl; Bh=g_wvh; Bl=g_wvl; dh=g_pkv[2]; dl=g_pkv[3]; bias=bv; scale=1.0f; }

    const int n0 = blockIdx.x * 128, m0 = blockIdx.y * 128;
    const int tid = threadIdx.x, lane = tid & 31, wid = tid >> 5;
    const int wm = wid & 3, wn = wid >> 2;

    float acc[2][8][4] = {};
    gemm_compute(Ah, Al, Bh, Bl, m0, n0, sb, tid, acc);

    #pragma unroll
    for (int nt = 0; nt < 8; ++nt) {
        int n = n0 + wn * 64 + nt * 8 + (lane & 3) * 2;
        float b0v = bias[n], b1v = bias[n + 1];
        int hd = n >> 6, d = n & 63;
        #pragma unroll
        for (int mt = 0; mt < 2; ++mt) {
            #pragma unroll
            for (int half = 0; half < 2; ++half) {
                int m = m0 + wm * 32 + mt * 16 + (lane >> 2) + 8 * half;
                float x = (acc[mt][nt][2*half+0] + b0v) * scale;
                float y = (acc[mt][nt][2*half+1] + b1v) * scale;
                unsigned hi, lo; split2(x, y, hi, lo);
                size_t dst = ((size_t)((m >> 11) * NHEAD + hd) * SEQ + (m & (SEQ-1))) * DK + d;
                *(unsigned*)(dh + dst) = hi;
                *(unsigned*)(dl + dst) = lo;
            }
        }
    }
}

// ---------------- output projection: grid (8, 32) --------------------------
__global__ __launch_bounds__(256) void tc_out(
    const float* __restrict__ bias, float* __restrict__ out)
{
    extern __shared__ char smem[];
    const unsigned sb = smem_u32(smem);
    const int n0 = blockIdx.x * 128, m0 = blockIdx.y * 128;
    const int tid = threadIdx.x, lane = tid & 31, wid = tid >> 5;
    const int wm = wid & 3, wn = wid >> 2;

    float acc[2][8][4] = {};
    gemm_compute(g_po[0], g_po[1], g_woh, g_wol, m0, n0, sb, tid, acc);

    #pragma unroll
    for (int nt = 0; nt < 8; ++nt) {
        int n = n0 + wn * 64 + nt * 8 + (lane & 3) * 2;
        float b0v = bias[n], b1v = bias[n + 1];
        #pragma unroll
        for (int mt = 0; mt < 2; ++mt) {
            #pragma unroll
            for (int half = 0; half < 2; ++half) {
                int m = m0 + wm * 32 + mt * 16 + (lane >> 2) + 8 * half;
                float2 vv = make_float2(acc[mt][nt][2*half+0] + b0v,
                                        acc[mt][nt][2*half+1] + b1v);
                *(float2*)(out + (size_t)m * D_MODEL + n) = vv;
            }
        }
    }
}

// ---------------- flash attention on HMMA: grid (32, 16, 2), 128 thr -------
// Br=64 (warp w owns rows 16w..16w+15), Bc=32 kv-rows/tile, 64 tiles.
// Q fragments in registers. SMEM: 3 KV stages x 16KB = 48KB -> 4 CTAs/SM
// (launch_bounds(128,4), 128-reg cap). physchunk = dc ^ (row&7).
#define A_STAGE 16384
#define A_SMEM  (3*A_STAGE)

__device__ __forceinline__ void attn_load_stage(
    unsigned st, const __nv_bfloat16* kvbase, int tid)
{
    #pragma unroll
    for (int tt = 0; tt < 4; ++tt) {
        const __nv_bfloat16* s = kvbase + (size_t)tt * NELEM;
        #pragma unroll
        for (int i = 0; i < 2; ++i) {
            int idx = tid + i * 128;         // 0..255 chunks (32 rows x 8)
            int row = idx >> 3, dc = idx & 7;
            unsigned d = st + tt * 4096 + row * 128 + (((dc ^ (row & 7))) << 4);
            cp16(d, s + (size_t)row * DK + dc * 8);
        }
    }
}

__global__ void __launch_bounds__(128, 4) attn_mma() {
    extern __shared__ char smem[];
    const unsigned sb = smem_u32(smem);
    const int tid = threadIdx.x, lane = tid & 31, w = tid >> 5;
    const int qt = blockIdx.x, h = blockIdx.y, b = blockIdx.z;

    const size_t headoff = ((size_t)(b * NHEAD + h)) * SEQ * DK;
    const __nv_bfloat16* qbase  = &g_pq[0][0]  + headoff + (size_t)qt * 64 * DK;
    const __nv_bfloat16* kvbase = &g_pkv[0][0] + headoff;

    // ---- prologue: stage Q through smem stage-0, park fragments in regs ----
    #pragma unroll
    for (int tile = 0; tile < 2; ++tile)
        #pragma unroll
        for (int i = 0; i < 4; ++i) {
            int idx = tid + i * 128;         // 0..511 (64 rows x 8)
            int row = idx >> 3, dc = idx & 7;
            cp16(sb + tile * 8192 + row * 128 + (((dc ^ (row & 7))) << 4),
                 qbase + (size_t)tile * NELEM + (size_t)row * DK + dc * 8);
        }
    CP_COMMIT(); CP_WAIT0();
    __syncthreads();

    unsigned qh_f[4][4], ql_f[4][4];
    #pragma unroll
    for (int ks = 0; ks < 4; ++ks) {
        int row = 16 * w + (lane & 15);
        int dc  = 2 * ks + (lane >> 4);
        unsigned off = row * 128 + (((dc ^ (row & 7))) << 4);
        LDSM4(qh_f[ks], sb + off);
        LDSM4(ql_f[ks], sb + 8192 + off);
    }
    __syncthreads();   // stage-0 free before KV pipeline reuses it

    attn_load_stage(sb,           kvbase, tid);            CP_COMMIT();
    attn_load_stage(sb + A_STAGE, kvbase + 32 * DK, tid);  CP_COMMIT();

    float s_m[2] = {-1e30f, -1e30f}, s_l[2] = {0.f, 0.f};
    float o[8][4] = {};

    for (int t = 0; t < 64; ++t) {
        CP_WAIT1();
        __syncthreads();
        if (t + 2 < 64)
            attn_load_stage(sb + ((t + 2) % 3) * A_STAGE,
                            kvbase + (size_t)(t + 2) * 32 * DK, tid);
        CP_COMMIT();
        const unsigned st = sb + (t % 3) * A_STAGE;

        // ---- S = Q K^T (3-term; Q pre-scaled by 0.125*log2e) ----
        float s[4][4] = {};
        #pragma unroll
        for (int ks = 0; ks < 4; ++ks) {
            #pragma unroll
            for (int q4 = 0; q4 < 2; ++q4) {
                unsigned bh[4], bl[4];
                int krow = q4 * 16 + (lane & 7) + 8 * ((lane >> 4) & 1);
                int kdc  = 2 * ks + ((lane >> 3) & 1);
                unsigned off = krow * 128 + (((kdc ^ (krow & 7))) << 4);
                LDSM4(bh, st + off);
                LDSM4(bl, st + 4096 + off);
                MMA4(s[2*q4],   qh_f[ks], bh[0], bh[1]);
                MMA4(s[2*q4],   qh_f[ks], bl[0], bl[1]);
                MMA4(s[2*q4],   ql_f[ks], bh[0], bh[1]);
                MMA4(s[2*q4+1], qh_f[ks], bh[2], bh[3]);
                MMA4(s[2*q4+1], qh_f[ks], bl[2], bl[3]);
                MMA4(s[2*q4+1], ql_f[ks], bh[2], bh[3]);
            }
        }

        // ---- online softmax (base-2 domain) ----
        #pragma unroll
        for (int r = 0; r < 2; ++r) {
            float mx = -1e30f;
            #pragma unroll
            for (int nt = 0; nt < 4; ++nt)
                mx = fmaxf(mx, fmaxf(s[nt][2*r], s[nt][2*r+1]));
            mx = fmaxf(mx, __shfl_xor_sync(0xffffffffu, mx, 1));
            mx = fmaxf(mx, __shfl_xor_sync(0xffffffffu, mx, 2));
            float mnew  = fmaxf(s_m[r], mx);
            float alpha = fexp2(s_m[r] - mnew);
            float rs = 0.f;
            #pragma unroll
            for (int nt = 0; nt < 4; ++nt) {
                float p0 = fexp2(s[nt][2*r]   - mnew);
                float p1 = fexp2(s[nt][2*r+1] - mnew);
                s[nt][2*r] = p0; s[nt][2*r+1] = p1;
                rs += p0 + p1;
            }
            rs += __shfl_xor_sync(0xffffffffu, rs, 1);
            rs += __shfl_xor_sync(0xffffffffu, rs, 2);
            s_l[r] = s_l[r] * alpha + rs;
            s_m[r] = mnew;
            #pragma unroll
            for (int nt = 0; nt < 8; ++nt) { o[nt][2*r] *= alpha; o[nt][2*r+1] *= alpha; }
        }

        // ---- O += P V (P repacked as A-frags; V via ldmatrix.trans) ----
        #pragma unroll
        for (int ks = 0; ks < 2; ++ks) {
            unsigned pa_h[4], pa_l[4];
            #pragma unroll
            for (int e = 0; e < 4; ++e) {
                int nt = 2 * ks + (e >> 1);
                float x = s[nt][(e & 1) * 2], y = s[nt][(e & 1) * 2 + 1];
                split2(x, y, pa_h[e], pa_l[e]);
            }
            #pragma unroll
            for (int d4 = 0; d4 < 4; ++d4) {
                unsigned vhf[4], vlf[4];
                int vrow = 16 * ks + (lane & 15);
                int vdc  = 2 * d4 + (lane >> 4);
                unsigned off = vrow * 128 + (((vdc ^ (vrow & 7))) << 4);
                LDSM4T(vhf, st + 8192  + off);
                LDSM4T(vlf, st + 12288 + off);
                MMA4(o[2*d4],   pa_h, vhf[0], vhf[1]);
                MMA4(o[2*d4],   pa_h, vlf[0], vlf[1]);
                MMA4(o[2*d4],   pa_l, vhf[0], vhf[1]);
                MMA4(o[2*d4+1], pa_h, vhf[2], vhf[3]);
                MMA4(o[2*d4+1], pa_h, vlf[2], vlf[3]);
                MMA4(o[2*d4+1], pa_l, vhf[2], vhf[3]);
            }
        }
    }

    // ---- epilogue: O/l, split to bf16 h/l at [b][s][h*64+d] ----
    float inv[2] = {1.f / s_l[0], 1.f / s_l[1]};
    __nv_bfloat16* pobase = &g_po[0][0];
    #pragma unroll
    for (int nt = 0; nt < 8; ++nt) {
        int d = h * DK + nt * 8 + (lane & 3) * 2;
        #pragma unroll
        for (int r = 0; r < 2; ++r) {
            int srow = qt * 64 + 16 * w + (lane >> 2) + 8 * r;
            float x = o[nt][2*r] * inv[r], y = o[nt][2*r+1] * inv[r];
            unsigned hi, lo; split2(x, y, hi, lo);
            size_t dst = (size_t)(b * SEQ + srow) * D_MODEL + d;
            *(unsigned*)(pobase + dst)         = hi;
            *(unsigned*)(pobase + NELEM + dst) = lo;
        }
    }
}

// ---------------- launcher --------------------------------------------------
extern "C" void kernel_launch(void* const* d_in, const int* in_sizes, int n_in,
                              void* d_out, int out_size) {
    const float* query = (const float*)d_in[0];
    const float* key   = (const float*)d_in[1];
    const float* value = (const float*)d_in[2];
    const float* Wq    = (const float*)d_in[3];
    const float* bq    = (const float*)d_in[4];
    const float* Wk    = (const float*)d_in[5];
    const float* bk    = (const float*)d_in[6];
    const float* Wv    = (const float*)d_in[7];
    const float* bv    = (const float*)d_in[8];
    const float* Wo    = (const float*)d_in[9];
    const float* bo    = (const float*)d_in[10];
    float* out = (float*)d_out;

    cudaFuncSetAttribute(tc_qkv,   cudaFuncAttributeMaxDynamicSharedMemorySize, G_SMEM);
    cudaFuncSetAttribute(tc_out,   cudaFuncAttributeMaxDynamicSharedMemorySize, G_SMEM);
    cudaFuncSetAttribute(attn_mma, cudaFuncAttributeMaxDynamicSharedMemorySize, A_SMEM);

    dim3 gS(592, 7);
    split_all<<<gS, 256>>>(query, key, value, Wq, Wk, Wv, Wo);

    dim3 gQKV(D_MODEL / 128, MTOT / 128, 3);   // (8, 32, 3)
    tc_qkv<<<gQKV, 256, G_SMEM>>>(bq, bk, bv);

    dim3 gAtt(SEQ / 64, NHEAD, BATCH);         // (32, 16, 2)
    attn_mma<<<gAtt, 128, A_SMEM>>>();

    dim3 gOut(D_MODEL / 128, MTOT / 128, 1);   // (8, 32)
    tc_out<<<gOut, 256, G_SMEM>>>(bo, out);
}